// round 9
// baseline (speedup 1.0000x reference)
#include <cuda_runtime.h>
#include <cuda_bf16.h>
#include <math.h>
#include <stdint.h>

#define B_  2
#define N_  1024
#define T_  8
#define D_  128
#define H_  4
#define E_  8192
#define M_  16384
#define MAXDEG 128

// ---------------- scratch (device globals) ----------------------------------
__device__ __align__(256) float g_xlr[(size_t)M_ * 1024];   // [xl(512)|xr(512)]
__device__ __align__(256) float g_qkv[(size_t)M_ * 384];
__device__ __align__(256) float g_attno[(size_t)M_ * 128];
__device__ __align__(256) float g_oproj[(size_t)M_ * 128];
__device__ __align__(256) float g_x1[(size_t)M_ * 128];
__device__ __align__(256) float g_hid[(size_t)M_ * 512];
__device__ __align__(256) float g_f2[(size_t)M_ * 128];
__device__ __align__(256) float g_cat[(size_t)M_ * 256];    // [x_sp | x_tp]
__device__ __align__(256) float g_gate[(size_t)M_ * 128];
// packed tf32 weights, [n][k] layout (pre-rounded via cvt.rna)
__device__ __align__(256) float g_Bxq[1408 * 128];          // [Wl|Wr|Wqkv]
__device__ __align__(256) float g_bias_xq[1408];
__device__ __align__(256) float g_Bout[128 * 128];
__device__ __align__(256) float g_Bffn1[512 * 128];
__device__ __align__(256) float g_Bffn2[128 * 512];
__device__ __align__(256) float g_Bfus[128 * 256];
// CSR
__device__ int g_deg[N_];
__device__ int g_csr[N_ * MAXDEG];

// ---------------- helpers ------------------------------------------------------
__device__ __forceinline__ float warp_sum(float v) {
#pragma unroll
    for (int o = 16; o; o >>= 1) v += __shfl_xor_sync(0xFFFFFFFFu, v, o);
    return v;
}
__device__ __forceinline__ uint32_t smem_u32(const void* p) {
    uint32_t a;
    asm("{ .reg .u64 t; cvta.to.shared.u64 t, %1; cvt.u32.u64 %0, t; }"
        : "=r"(a) : "l"(p));
    return a;
}
#define CP16(dst, src) \
    asm volatile("cp.async.cg.shared.global [%0], [%1], 16;" :: "r"(dst), "l"(src))
#define CVT_TF32(u, f) asm("cvt.rna.tf32.f32 %0, %1;" : "=r"(u) : "f"(f))

__device__ __forceinline__ void mma_tf32(float c[4], const uint32_t a[4],
                                         const uint32_t b[2]) {
    asm volatile(
        "mma.sync.aligned.m16n8k8.row.col.f32.tf32.tf32.f32 "
        "{%0,%1,%2,%3}, {%4,%5,%6,%7}, {%8,%9}, {%0,%1,%2,%3};"
        : "+f"(c[0]), "+f"(c[1]), "+f"(c[2]), "+f"(c[3])
        : "r"(a[0]), "r"(a[1]), "r"(a[2]), "r"(a[3]), "r"(b[0]), "r"(b[1]));
}

// ---------------- init + CSR + bias_xq -------------------------------------------
__global__ void k_init0(const float* __restrict__ in_b) {
    int i = blockIdx.x * blockDim.x + threadIdx.x;
    if (i < N_) { g_deg[i] = 1; g_csr[i * MAXDEG] = i; }   // self loop
    if (i < 1408) g_bias_xq[i] = (i < 1024) ? 0.f : in_b[i - 1024];
}
__global__ void k_scatter(const int* __restrict__ edges) {
    int e = blockIdx.x * blockDim.x + threadIdx.x;
    if (e >= E_) return;
    int s = edges[e], d = edges[E_ + e];
    int pos = atomicAdd(&g_deg[d], 1);
    if (pos < MAXDEG) g_csr[d * MAXDEG + pos] = s;
}

// ---------------- weight packing: transpose to [n][k], round to tf32 -------------
__global__ void k_packw(const float* wl, const float* wr, const float* inw,
                        const float* outw, const float* f1w, const float* f2w,
                        const float* fw) {
    int job = blockIdx.y;
    int idx = blockIdx.x * 256 + threadIdx.x;
    const float* W; float* Bo; int K, Nw, coff = 0;
    switch (job) {
        case 0: W = wl;   Bo = g_Bxq;   K = 128; Nw = 512; break;
        case 1: W = wr;   Bo = g_Bxq;   K = 128; Nw = 512; coff = 512; break;
        case 2: W = inw;  Bo = g_Bxq;   K = 128; Nw = 384; coff = 1024; break;
        case 3: W = outw; Bo = g_Bout;  K = 128; Nw = 128; break;
        case 4: W = f1w;  Bo = g_Bffn1; K = 128; Nw = 512; break;
        case 5: W = f2w;  Bo = g_Bffn2; K = 512; Nw = 128; break;
        default:W = fw;   Bo = g_Bfus;  K = 256; Nw = 128; break;
    }
    if (idx >= K * Nw) return;
    int k = idx / Nw, n = idx % Nw;
    uint32_t u;
    CVT_TF32(u, W[idx]);
    Bo[(size_t)(coff + n) * K + k] = __uint_as_float(u);
}

// ---------------- tf32 mma.sync GEMM -----------------------------------------------
// C = A(fp32 MxK) @ W(tf32 packed [n][k])
// CTA tile 64x128, 128 thr (2x2 warps, warp tile 32x64), K-panels 16, 3-stage.
// 4 CTAs/SM for cross-CTA latency hiding.
// mode 1: +bias; 2: +bias+GELU; 3: +bias+sigmoid. Dual dest: col<N1 -> C1 else C2.
#define KP 20
#define APLANE (64 * KP)
#define BPLANE (128 * KP)
#define SMEMSZ ((APLANE + BPLANE) * 3 * 4)

__global__ void __launch_bounds__(128, 4) hgemm(
        const float* __restrict__ A, const float* __restrict__ Bp,
        const float* __restrict__ bias,
        float* __restrict__ C1, int N1, int s1,
        float* __restrict__ C2, int s2,
        int K, int mode) {
    extern __shared__ float sm[];
    float* sA = sm;                    // [3][64][KP]
    float* sB = sm + 3 * APLANE;       // [3][128][KP]
    int tid = threadIdx.x, wid = tid >> 5, lane = tid & 31;
    int wm = wid >> 1, wn = wid & 1;   // 2x2 warp grid
    int rowBase = blockIdx.y * 64, colBase = blockIdx.x * 128;
    int nk = K >> 4;

    float acc[2][8][4];
#pragma unroll
    for (int i = 0; i < 2; i++)
#pragma unroll
        for (int j = 0; j < 8; j++)
#pragma unroll
            for (int q = 0; q < 4; q++) acc[i][j][q] = 0.f;

    // loaders (128 threads): A 64x16 f32 (2 CP16/thr), B 128x16 f32 (4 CP16/thr)
    int ar = tid >> 1, aq = tid & 1;            // A row, k-half (8 floats each)
    const char* Asrc = (const char*)(A + (size_t)(rowBase + ar) * K + aq * 8);
    const char* Bsrc = (const char*)(Bp + (size_t)(colBase + tid) * K);
    uint32_t dA = smem_u32(sA) + (uint32_t)(ar * KP + aq * 8) * 4;
    uint32_t dB = smem_u32(sB) + (uint32_t)(tid * KP) * 4;

    auto ld = [&](int kt, int buf) {
        const char* as = Asrc + (size_t)kt * 64;
        CP16(dA + buf * (APLANE * 4), as);
        CP16(dA + buf * (APLANE * 4) + 16, as + 16);
        const char* bs = Bsrc + (size_t)kt * 64;
        uint32_t db = dB + buf * (BPLANE * 4);
        CP16(db, bs); CP16(db + 16, bs + 16);
        CP16(db + 32, bs + 32); CP16(db + 48, bs + 48);
        asm volatile("cp.async.commit_group;" ::: "memory");
    };

    ld(0, 0);
    if (nk > 1) ld(1, 1);

    // per-warp fragment base pointers
    int fr = lane >> 2, fq = lane & 3;
    const float* awp = sA + (wm * 32 + fr) * KP + fq;
    const float* bwp = sB + (wn * 64 + fr) * KP + fq;

    for (int kt = 0; kt < nk; kt++) {
        int buf = kt % 3;
        if (kt + 1 < nk) asm volatile("cp.async.wait_group 1;" ::: "memory");
        else             asm volatile("cp.async.wait_group 0;" ::: "memory");
        __syncthreads();
        if (kt + 2 < nk) ld(kt + 2, (kt + 2) % 3);

        const float* aw = awp + buf * APLANE;
        const float* bw = bwp + buf * BPLANE;
#pragma unroll
        for (int k8 = 0; k8 < 2; k8++) {
            uint32_t ua[2][4], ub[8][2];
#pragma unroll
            for (int mi = 0; mi < 2; mi++) {
                const float* ap = aw + mi * (16 * KP) + k8 * 8;
                CVT_TF32(ua[mi][0], ap[0]);
                CVT_TF32(ua[mi][1], ap[8 * KP]);
                CVT_TF32(ua[mi][2], ap[4]);
                CVT_TF32(ua[mi][3], ap[8 * KP + 4]);
            }
#pragma unroll
            for (int ni = 0; ni < 8; ni++) {
                const float* bp = bw + ni * (8 * KP) + k8 * 8;
                ub[ni][0] = __float_as_uint(bp[0]);
                ub[ni][1] = __float_as_uint(bp[4]);
            }
#pragma unroll
            for (int mi = 0; mi < 2; mi++)
#pragma unroll
                for (int ni = 0; ni < 8; ni++)
                    mma_tf32(acc[mi][ni], ua[mi], ub[ni]);
        }
    }

    // ---- epilogue ----
    int fc2 = (lane & 3) * 2;
#pragma unroll
    for (int mi = 0; mi < 2; mi++) {
        int r0 = rowBase + wm * 32 + mi * 16 + fr;
#pragma unroll
        for (int ni = 0; ni < 8; ni++) {
            int col = colBase + wn * 64 + ni * 8 + fc2;
            float b0 = bias[col], b1 = bias[col + 1];
            float v[4] = {acc[mi][ni][0] + b0, acc[mi][ni][1] + b1,
                          acc[mi][ni][2] + b0, acc[mi][ni][3] + b1};
            if (mode == 2) {
#pragma unroll
                for (int q = 0; q < 4; q++)
                    v[q] = 0.5f * v[q] * (1.f + erff(v[q] * 0.70710678118654752f));
            } else if (mode == 3) {
#pragma unroll
                for (int q = 0; q < 4; q++) v[q] = 1.f / (1.f + __expf(-v[q]));
            }
            if (col < N1) {
                *(float2*)&C1[(size_t)r0 * s1 + col]       = make_float2(v[0], v[1]);
                *(float2*)&C1[(size_t)(r0 + 8) * s1 + col] = make_float2(v[2], v[3]);
            } else {
                int c2 = col - N1;
                *(float2*)&C2[(size_t)r0 * s2 + c2]        = make_float2(v[0], v[1]);
                *(float2*)&C2[(size_t)(r0 + 8) * s2 + c2]  = make_float2(v[2], v[3]);
            }
        }
    }
}

// ---------------- LayerNorm compute ---------------------------------------------
__device__ __forceinline__ float4 ln_compute(float4 v, const float* g, const float* b,
                                             int lane) {
    float mean = warp_sum(v.x + v.y + v.z + v.w) * (1.f / 128.f);
    float4 c = make_float4(v.x - mean, v.y - mean, v.z - mean, v.w - mean);
    float var = warp_sum(c.x * c.x + c.y * c.y + c.z * c.z + c.w * c.w) * (1.f / 128.f);
    float rs = rsqrtf(var + 1e-5f);
    float4 gv = *(const float4*)&g[lane * 4];
    float4 bv = *(const float4*)&b[lane * 4];
    return make_float4(c.x * rs * gv.x + bv.x, c.y * rs * gv.y + bv.y,
                       c.z * rs * gv.z + bv.z, c.w * rs * gv.w + bv.w);
}

// ---------------- fused GAT (online softmax, dst-centric) --------------------------
__global__ void k_gat(const float* __restrict__ att, const float* __restrict__ gat_b,
                      const float* __restrict__ lg, const float* __restrict__ lb) {
    int w = (blockIdx.x * blockDim.x + threadIdx.x) >> 5;   // row = (b*N+n)*T+t
    int lane = threadIdx.x & 31;
    if (w >= M_) return;
    int bn = w >> 3;
    int n = bn & (N_ - 1);
    int b = bn >> 10;
    int t = w & 7;

    const float4* xr4 = (const float4*)(g_xlr + (size_t)w * 1024 + 512);
    float4 xr[4], av[4];
#pragma unroll
    for (int h = 0; h < 4; h++) {
        xr[h] = xr4[h * 32 + lane];
        av[h] = ((const float4*)att)[h * 32 + lane];
    }
    float4 acc[4];
#pragma unroll
    for (int h = 0; h < 4; h++) acc[h] = make_float4(0.f, 0.f, 0.f, 0.f);
    float m[4] = {-INFINITY, -INFINITY, -INFINITY, -INFINITY};
    float s[4] = {0.f, 0.f, 0.f, 0.f};

    int deg = g_deg[n];
    if (deg > MAXDEG) deg = MAXDEG;
    const int* clist = g_csr + n * MAXDEG;

    for (int i = 0; i < deg; i++) {
        int src = clist[i];
        const float4* xl4 = (const float4*)(g_xlr + ((size_t)((b * N_ + src) * T_ + t)) * 1024);
        float4 xl[4];
        float lgt[4];
#pragma unroll
        for (int h = 0; h < 4; h++) {
            float4 a = xl4[h * 32 + lane];
            xl[h] = a;
            float v0 = a.x + xr[h].x; v0 = v0 > 0.f ? v0 : 0.2f * v0;
            float v1 = a.y + xr[h].y; v1 = v1 > 0.f ? v1 : 0.2f * v1;
            float v2 = a.z + xr[h].z; v2 = v2 > 0.f ? v2 : 0.2f * v2;
            float v3 = a.w + xr[h].w; v3 = v3 > 0.f ? v3 : 0.2f * v3;
            lgt[h] = warp_sum(av[h].x * v0 + av[h].y * v1 + av[h].z * v2 + av[h].w * v3);
        }
#pragma unroll
        for (int h = 0; h < 4; h++) {
            float nm = fmaxf(m[h], lgt[h]);
            float e0 = __expf(m[h] - nm);
            float e1 = __expf(lgt[h] - nm);
            s[h] = s[h] * e0 + e1;
            acc[h].x = acc[h].x * e0 + e1 * xl[h].x;
            acc[h].y = acc[h].y * e0 + e1 * xl[h].y;
            acc[h].z = acc[h].z * e0 + e1 * xl[h].z;
            acc[h].w = acc[h].w * e0 + e1 * xl[h].w;
            m[h] = nm;
        }
    }

    float4 o = make_float4(0.f, 0.f, 0.f, 0.f);
#pragma unroll
    for (int h = 0; h < 4; h++) {
        float r = 0.25f / s[h];
        o.x += acc[h].x * r; o.y += acc[h].y * r;
        o.z += acc[h].z * r; o.w += acc[h].w * r;
    }
    float4 gb = *(const float4*)&gat_b[lane * 4];
    o.x += gb.x; o.y += gb.y; o.z += gb.z; o.w += gb.w;

    float4 r4 = ln_compute(o, lg, lb, lane);
    *(float4*)&g_cat[(size_t)w * 256 + lane * 4] = r4;
}

// ---------------- residual LNs ------------------------------------------------------
__global__ void k_lnt1(const float* __restrict__ x,
                       const float* __restrict__ g, const float* __restrict__ b) {
    int row = (blockIdx.x * blockDim.x + threadIdx.x) >> 5;
    int lane = threadIdx.x & 31;
    if (row >= M_) return;
    float4 v  = *(const float4*)&x[(size_t)row * D_ + lane * 4];
    float4 v2 = *(const float4*)&g_oproj[(size_t)row * D_ + lane * 4];
    v.x += v2.x; v.y += v2.y; v.z += v2.z; v.w += v2.w;
    float4 r4 = ln_compute(v, g, b, lane);
    *(float4*)&g_x1[(size_t)row * D_ + lane * 4] = r4;
}

__global__ void k_lnt2(const float* __restrict__ g, const float* __restrict__ b) {
    int row = (blockIdx.x * blockDim.x + threadIdx.x) >> 5;
    int lane = threadIdx.x & 31;
    if (row >= M_) return;
    float4 v  = *(const float4*)&g_x1[(size_t)row * D_ + lane * 4];
    float4 v2 = *(const float4*)&g_f2[(size_t)row * D_ + lane * 4];
    v.x += v2.x; v.y += v2.y; v.z += v2.z; v.w += v2.w;
    float4 r4 = ln_compute(v, g, b, lane);
    *(float4*)&g_cat[(size_t)row * 256 + 128 + lane * 4] = r4;
}

__global__ void k_final(const float* __restrict__ x,
                        const float* __restrict__ g, const float* __restrict__ b,
                        float* __restrict__ out) {
    int row = (blockIdx.x * blockDim.x + threadIdx.x) >> 5;
    int lane = threadIdx.x & 31;
    if (row >= M_) return;
    float4 xsp = *(const float4*)&g_cat[(size_t)row * 256 + lane * 4];
    float4 xtp = *(const float4*)&g_cat[(size_t)row * 256 + 128 + lane * 4];
    float4 gt  = *(const float4*)&g_gate[(size_t)row * D_ + lane * 4];
    float4 xv  = *(const float4*)&x[(size_t)row * D_ + lane * 4];
    float4 v = make_float4(gt.x * xsp.x + (1.f - gt.x) * xtp.x + xv.x,
                           gt.y * xsp.y + (1.f - gt.y) * xtp.y + xv.y,
                           gt.z * xsp.z + (1.f - gt.z) * xtp.z + xv.z,
                           gt.w * xsp.w + (1.f - gt.w) * xtp.w + xv.w);
    float4 r4 = ln_compute(v, g, b, lane);
    *(float4*)&out[(size_t)row * D_ + lane * 4] = r4;
}

// ---------------- temporal attention ------------------------------------------------
__global__ void k_attn() {
    int w = blockIdx.x * 4 + (threadIdx.x >> 5);
    int lane = threadIdx.x & 31;
    if (w >= (B_ * N_) * H_) return;
    int bn = w >> 2;
    int h = w & 3;
    float q[8], k[8], v[8];
#pragma unroll
    for (int t = 0; t < 8; t++) {
        size_t base = ((size_t)bn * 8 + t) * 384 + h * 32 + lane;
        q[t] = g_qkv[base];
        k[t] = g_qkv[base + 128];
        v[t] = g_qkv[base + 256];
    }
    const float scale = 0.17677669529663687f;
#pragma unroll
    for (int t = 0; t < 8; t++) {
        float sc[8];
#pragma unroll
        for (int s = 0; s < 8; s++) sc[s] = warp_sum(q[t] * k[s]) * scale;
        float mx = sc[0];
#pragma unroll
        for (int s = 1; s < 8; s++) mx = fmaxf(mx, sc[s]);
        float den = 0.f;
#pragma unroll
        for (int s = 0; s < 8; s++) { sc[s] = __expf(sc[s] - mx); den += sc[s]; }
        float inv = 1.f / den;
        float o = 0.f;
#pragma unroll
        for (int s = 0; s < 8; s++) o += sc[s] * v[s];
        g_attno[((size_t)bn * 8 + t) * D_ + h * 32 + lane] = o * inv;
    }
}

// ---------------- launch ---------------------------------------------------------------
extern "C" void kernel_launch(void* const* d_in, const int* in_sizes, int n_in,
                              void* d_out, int out_size) {
    const float* x      = (const float*)d_in[0];
    const int*   edges  = (const int*)  d_in[1];
    const float* gat_att= (const float*)d_in[4];
    const float* gat_b  = (const float*)d_in[5];
    const float* in_b   = (const float*)d_in[7];
    const float* out_b  = (const float*)d_in[9];
    const float* ffn_b1 = (const float*)d_in[11];
    const float* ffn_b2 = (const float*)d_in[13];
    const float* fus_b  = (const float*)d_in[15];
    const float* lns_g  = (const float*)d_in[16];
    const float* lns_b  = (const float*)d_in[17];
    const float* lnt1_g = (const float*)d_in[18];
    const float* lnt1_b = (const float*)d_in[19];
    const float* lnt2_g = (const float*)d_in[20];
    const float* lnt2_b = (const float*)d_in[21];
    const float* lnf_g  = (const float*)d_in[22];
    const float* lnf_b  = (const float*)d_in[23];
    float* out = (float*)d_out;

    float *p_xlr, *p_qkv, *p_attno, *p_oproj, *p_x1, *p_hid, *p_f2, *p_cat, *p_gate;
    float *p_bxq, *p_Bxq, *p_Bout, *p_Bffn1, *p_Bffn2, *p_Bfus;
    cudaGetSymbolAddress((void**)&p_xlr,   g_xlr);
    cudaGetSymbolAddress((void**)&p_qkv,   g_qkv);
    cudaGetSymbolAddress((void**)&p_attno, g_attno);
    cudaGetSymbolAddress((void**)&p_oproj, g_oproj);
    cudaGetSymbolAddress((void**)&p_x1,    g_x1);
    cudaGetSymbolAddress((void**)&p_hid,   g_hid);
    cudaGetSymbolAddress((void**)&p_f2,    g_f2);
    cudaGetSymbolAddress((void**)&p_cat,   g_cat);
    cudaGetSymbolAddress((void**)&p_gate,  g_gate);
    cudaGetSymbolAddress((void**)&p_bxq,   g_bias_xq);
    cudaGetSymbolAddress((void**)&p_Bxq,   g_Bxq);
    cudaGetSymbolAddress((void**)&p_Bout,  g_Bout);
    cudaGetSymbolAddress((void**)&p_Bffn1, g_Bffn1);
    cudaGetSymbolAddress((void**)&p_Bffn2, g_Bffn2);
    cudaGetSymbolAddress((void**)&p_Bfus,  g_Bfus);

    cudaFuncSetAttribute(hgemm, cudaFuncAttributeMaxDynamicSharedMemorySize, SMEMSZ);

    // prep
    k_init0<<<6, 256>>>(in_b);
    k_scatter<<<E_ / 256, 256>>>(edges);
    k_packw<<<dim3(256, 7), 256>>>((const float*)d_in[2], (const float*)d_in[3],
                                   (const float*)d_in[6], (const float*)d_in[8],
                                   (const float*)d_in[10], (const float*)d_in[12],
                                   (const float*)d_in[14]);

    // merged spatial+qkv: [xlr | qkv] = x @ [Wl|Wr|Wqkv]
    hgemm<<<dim3(11, 256), 128, SMEMSZ>>>(x, p_Bxq, p_bxq,
                                          p_xlr, 1024, 1024, p_qkv, 384, 128, 1);
    k_gat<<<M_ / 8, 256>>>(gat_att, gat_b, lns_g, lns_b);

    // temporal
    k_attn<<<(B_ * N_ * H_) / 4, 128>>>();
    hgemm<<<dim3(1, 256), 128, SMEMSZ>>>(p_attno, p_Bout, out_b,
                                         p_oproj, 128, 128, p_oproj, 128, 128, 1);
    k_lnt1<<<M_ / 8, 256>>>(x, lnt1_g, lnt1_b);

    // FFN
    hgemm<<<dim3(4, 256), 128, SMEMSZ>>>(p_x1, p_Bffn1, ffn_b1,
                                         p_hid, 512, 512, p_hid, 512, 128, 2);
    hgemm<<<dim3(1, 256), 128, SMEMSZ>>>(p_hid, p_Bffn2, ffn_b2,
                                         p_f2, 128, 128, p_f2, 128, 512, 1);
    k_lnt2<<<M_ / 8, 256>>>(lnt2_g, lnt2_b);

    // fusion
    hgemm<<<dim3(1, 256), 128, SMEMSZ>>>(p_cat, p_Bfus, fus_b,
                                         p_gate, 128, 128, p_gate, 128, 256, 3);
    k_final<<<M_ / 8, 256>>>(x, lnf_g, lnf_b, out);
}

// round 10
// speedup vs baseline: 1.1145x; 1.1145x over previous
#include <cuda_runtime.h>
#include <cuda_bf16.h>
#include <math.h>
#include <stdint.h>

#define B_  2
#define N_  1024
#define T_  8
#define D_  128
#define H_  4
#define E_  8192
#define M_  16384
#define MAXDEG 128

// ---------------- scratch (device globals) ----------------------------------
__device__ __align__(256) float g_xlr[(size_t)M_ * 1024];   // [xl(512)|xr(512)]
__device__ __align__(256) float g_qkv[(size_t)M_ * 384];
__device__ __align__(256) float g_attno[(size_t)M_ * 128];
__device__ __align__(256) float g_oproj[(size_t)M_ * 128];
__device__ __align__(256) float g_x1[(size_t)M_ * 128];
__device__ __align__(256) float g_hid[(size_t)M_ * 512];
__device__ __align__(256) float g_f2[(size_t)M_ * 128];
__device__ __align__(256) float g_cat[(size_t)M_ * 256];    // [x_sp | x_tp]
__device__ __align__(256) float g_gate[(size_t)M_ * 128];
// packed tf32 weights, [n][k] layout (pre-rounded via cvt.rna)
__device__ __align__(256) float g_Bxq[1408 * 128];          // [Wl|Wr|Wqkv]
__device__ __align__(256) float g_bias_xq[1408];
__device__ __align__(256) float g_Bout[128 * 128];
__device__ __align__(256) float g_Bffn1[512 * 128];
__device__ __align__(256) float g_Bffn2[128 * 512];
__device__ __align__(256) float g_Bfus[128 * 256];
// CSR
__device__ int g_deg[N_];
__device__ int g_csr[N_ * MAXDEG];

// ---------------- helpers ------------------------------------------------------
__device__ __forceinline__ float warp_sum(float v) {
#pragma unroll
    for (int o = 16; o; o >>= 1) v += __shfl_xor_sync(0xFFFFFFFFu, v, o);
    return v;
}
__device__ __forceinline__ uint32_t smem_u32(const void* p) {
    uint32_t a;
    asm("{ .reg .u64 t; cvta.to.shared.u64 t, %1; cvt.u32.u64 %0, t; }"
        : "=r"(a) : "l"(p));
    return a;
}
#define CP16(dst, src) \
    asm volatile("cp.async.cg.shared.global [%0], [%1], 16;" :: "r"(dst), "l"(src))
#define CVT_TF32(u, f) asm("cvt.rna.tf32.f32 %0, %1;" : "=r"(u) : "f"(f))

__device__ __forceinline__ void mma_tf32(float c[4], const uint32_t a[4],
                                         const uint32_t b[2]) {
    asm volatile(
        "mma.sync.aligned.m16n8k8.row.col.f32.tf32.tf32.f32 "
        "{%0,%1,%2,%3}, {%4,%5,%6,%7}, {%8,%9}, {%0,%1,%2,%3};"
        : "+f"(c[0]), "+f"(c[1]), "+f"(c[2]), "+f"(c[3])
        : "r"(a[0]), "r"(a[1]), "r"(a[2]), "r"(a[3]), "r"(b[0]), "r"(b[1]));
}

// ---------------- init + CSR + bias_xq -------------------------------------------
__global__ void k_init0(const float* __restrict__ in_b) {
    int i = blockIdx.x * blockDim.x + threadIdx.x;
    if (i < N_) { g_deg[i] = 1; g_csr[i * MAXDEG] = i; }   // self loop
    if (i < 1408) g_bias_xq[i] = (i < 1024) ? 0.f : in_b[i - 1024];
}
__global__ void k_scatter(const int* __restrict__ edges) {
    int e = blockIdx.x * blockDim.x + threadIdx.x;
    if (e >= E_) return;
    int s = edges[e], d = edges[E_ + e];
    int pos = atomicAdd(&g_deg[d], 1);
    if (pos < MAXDEG) g_csr[d * MAXDEG + pos] = s;
}

// ---------------- weight packing: transpose to [n][k], round to tf32 -------------
__global__ void k_packw(const float* wl, const float* wr, const float* inw,
                        const float* outw, const float* f1w, const float* f2w,
                        const float* fw) {
    int job = blockIdx.y;
    int idx = blockIdx.x * 256 + threadIdx.x;
    const float* W; float* Bo; int K, Nw, coff = 0;
    switch (job) {
        case 0: W = wl;   Bo = g_Bxq;   K = 128; Nw = 512; break;
        case 1: W = wr;   Bo = g_Bxq;   K = 128; Nw = 512; coff = 512; break;
        case 2: W = inw;  Bo = g_Bxq;   K = 128; Nw = 384; coff = 1024; break;
        case 3: W = outw; Bo = g_Bout;  K = 128; Nw = 128; break;
        case 4: W = f1w;  Bo = g_Bffn1; K = 128; Nw = 512; break;
        case 5: W = f2w;  Bo = g_Bffn2; K = 512; Nw = 128; break;
        default:W = fw;   Bo = g_Bfus;  K = 256; Nw = 128; break;
    }
    if (idx >= K * Nw) return;
    int k = idx / Nw, n = idx % Nw;
    uint32_t u;
    CVT_TF32(u, W[idx]);
    Bo[(size_t)(coff + n) * K + k] = __uint_as_float(u);
}

// ---------------- tf32 mma.sync GEMM (R8 config: 256thr, 2 CTA/SM) ----------------
#define KP 20
#define APLANE (64 * KP)
#define BPLANE (128 * KP)
#define SMEMSZ ((APLANE + BPLANE) * 3 * 4)

__global__ void __launch_bounds__(256, 2) hgemm(
        const float* __restrict__ A, const float* __restrict__ Bp,
        const float* __restrict__ bias,
        float* __restrict__ C1, int N1, int s1,
        float* __restrict__ C2, int s2,
        int K, int mode) {
    extern __shared__ float sm[];
    float* sA = sm;                    // [3][64][KP]
    float* sB = sm + 3 * APLANE;       // [3][128][KP]
    int tid = threadIdx.x, wid = tid >> 5, lane = tid & 31;
    int wm = wid >> 2, wn = wid & 3;
    int rowBase = blockIdx.y * 64, colBase = blockIdx.x * 128;
    int nk = K >> 4;

    float acc[2][4][4];
#pragma unroll
    for (int i = 0; i < 2; i++)
#pragma unroll
        for (int j = 0; j < 4; j++)
#pragma unroll
            for (int q = 0; q < 4; q++) acc[i][j][q] = 0.f;

    int ar = tid >> 2, aq = tid & 3;
    int br = tid >> 1, bq = (tid & 1) * 2;
    const char* Asrc = (const char*)(A + (size_t)(rowBase + ar) * K + aq * 4);
    const char* Bsrc = (const char*)(Bp + (size_t)(colBase + br) * K + bq * 4);
    uint32_t dA = smem_u32(sA) + (uint32_t)(ar * KP + aq * 4) * 4;
    uint32_t dB = smem_u32(sB) + (uint32_t)(br * KP + bq * 4) * 4;

    auto ld = [&](int kt, int buf) {
        CP16(dA + buf * (APLANE * 4), Asrc + (size_t)kt * 64);
        CP16(dB + buf * (BPLANE * 4), Bsrc + (size_t)kt * 64);
        CP16(dB + buf * (BPLANE * 4) + 16, Bsrc + (size_t)kt * 64 + 16);
        asm volatile("cp.async.commit_group;" ::: "memory");
    };

    ld(0, 0);
    if (nk > 1) ld(1, 1);

    int fr = lane >> 2, fq = lane & 3;
    const float* awp = sA + (wm * 32 + fr) * KP + fq;
    const float* bwp = sB + (wn * 32 + fr) * KP + fq;

    for (int kt = 0; kt < nk; kt++) {
        int buf = kt % 3;
        if (kt + 1 < nk) asm volatile("cp.async.wait_group 1;" ::: "memory");
        else             asm volatile("cp.async.wait_group 0;" ::: "memory");
        __syncthreads();
        if (kt + 2 < nk) ld(kt + 2, (kt + 2) % 3);

        const float* aw = awp + buf * APLANE;
        const float* bw = bwp + buf * BPLANE;
#pragma unroll
        for (int k8 = 0; k8 < 2; k8++) {
            uint32_t ua[2][4], ub[4][2];
#pragma unroll
            for (int mi = 0; mi < 2; mi++) {
                const float* ap = aw + mi * (16 * KP) + k8 * 8;
                CVT_TF32(ua[mi][0], ap[0]);
                CVT_TF32(ua[mi][1], ap[8 * KP]);
                CVT_TF32(ua[mi][2], ap[4]);
                CVT_TF32(ua[mi][3], ap[8 * KP + 4]);
            }
#pragma unroll
            for (int ni = 0; ni < 4; ni++) {
                const float* bp = bw + ni * (8 * KP) + k8 * 8;
                ub[ni][0] = __float_as_uint(bp[0]);
                ub[ni][1] = __float_as_uint(bp[4]);
            }
#pragma unroll
            for (int mi = 0; mi < 2; mi++)
#pragma unroll
                for (int ni = 0; ni < 4; ni++)
                    mma_tf32(acc[mi][ni], ua[mi], ub[ni]);
        }
    }

    // ---- epilogue ----
    int fc2 = (lane & 3) * 2;
#pragma unroll
    for (int mi = 0; mi < 2; mi++) {
        int r0 = rowBase + wm * 32 + mi * 16 + fr;
#pragma unroll
        for (int ni = 0; ni < 4; ni++) {
            int col = colBase + wn * 32 + ni * 8 + fc2;
            float b0 = bias[col], b1 = bias[col + 1];
            float v[4] = {acc[mi][ni][0] + b0, acc[mi][ni][1] + b1,
                          acc[mi][ni][2] + b0, acc[mi][ni][3] + b1};
            if (mode == 2) {
#pragma unroll
                for (int q = 0; q < 4; q++)
                    v[q] = 0.5f * v[q] * (1.f + erff(v[q] * 0.70710678118654752f));
            } else if (mode == 3) {
#pragma unroll
                for (int q = 0; q < 4; q++) v[q] = 1.f / (1.f + __expf(-v[q]));
            }
            if (col < N1) {
                *(float2*)&C1[(size_t)r0 * s1 + col]       = make_float2(v[0], v[1]);
                *(float2*)&C1[(size_t)(r0 + 8) * s1 + col] = make_float2(v[2], v[3]);
            } else {
                int c2 = col - N1;
                *(float2*)&C2[(size_t)r0 * s2 + c2]        = make_float2(v[0], v[1]);
                *(float2*)&C2[(size_t)(r0 + 8) * s2 + c2]  = make_float2(v[2], v[3]);
            }
        }
    }
}

// ---------------- LayerNorm compute ---------------------------------------------
__device__ __forceinline__ float4 ln_compute(float4 v, const float* g, const float* b,
                                             int lane) {
    float mean = warp_sum(v.x + v.y + v.z + v.w) * (1.f / 128.f);
    float4 c = make_float4(v.x - mean, v.y - mean, v.z - mean, v.w - mean);
    float var = warp_sum(c.x * c.x + c.y * c.y + c.z * c.z + c.w * c.w) * (1.f / 128.f);
    float rs = rsqrtf(var + 1e-5f);
    float4 gv = *(const float4*)&g[lane * 4];
    float4 bv = *(const float4*)&b[lane * 4];
    return make_float4(c.x * rs * gv.x + bv.x, c.y * rs * gv.y + bv.y,
                       c.z * rs * gv.z + bv.z, c.w * rs * gv.w + bv.w);
}

// ---------------- fused GAT (online softmax, dst-centric) --------------------------
__global__ void k_gat(const float* __restrict__ att, const float* __restrict__ gat_b,
                      const float* __restrict__ lg, const float* __restrict__ lb) {
    int w = (blockIdx.x * blockDim.x + threadIdx.x) >> 5;   // row = (b*N+n)*T+t
    int lane = threadIdx.x & 31;
    if (w >= M_) return;
    int bn = w >> 3;
    int n = bn & (N_ - 1);
    int b = bn >> 10;
    int t = w & 7;

    const float4* xr4 = (const float4*)(g_xlr + (size_t)w * 1024 + 512);
    float4 xr[4], av[4];
#pragma unroll
    for (int h = 0; h < 4; h++) {
        xr[h] = xr4[h * 32 + lane];
        av[h] = ((const float4*)att)[h * 32 + lane];
    }
    float4 acc[4];
#pragma unroll
    for (int h = 0; h < 4; h++) acc[h] = make_float4(0.f, 0.f, 0.f, 0.f);
    float m[4] = {-INFINITY, -INFINITY, -INFINITY, -INFINITY};
    float s[4] = {0.f, 0.f, 0.f, 0.f};

    int deg = g_deg[n];
    if (deg > MAXDEG) deg = MAXDEG;
    const int* clist = g_csr + n * MAXDEG;

    for (int i = 0; i < deg; i++) {
        int src = clist[i];
        const float4* xl4 = (const float4*)(g_xlr + ((size_t)((b * N_ + src) * T_ + t)) * 1024);
        float4 xl[4];
        float lgt[4];
#pragma unroll
        for (int h = 0; h < 4; h++) {
            float4 a = xl4[h * 32 + lane];
            xl[h] = a;
            float v0 = a.x + xr[h].x; v0 = v0 > 0.f ? v0 : 0.2f * v0;
            float v1 = a.y + xr[h].y; v1 = v1 > 0.f ? v1 : 0.2f * v1;
            float v2 = a.z + xr[h].z; v2 = v2 > 0.f ? v2 : 0.2f * v2;
            float v3 = a.w + xr[h].w; v3 = v3 > 0.f ? v3 : 0.2f * v3;
            lgt[h] = warp_sum(av[h].x * v0 + av[h].y * v1 + av[h].z * v2 + av[h].w * v3);
        }
#pragma unroll
        for (int h = 0; h < 4; h++) {
            float nm = fmaxf(m[h], lgt[h]);
            float e0 = __expf(m[h] - nm);
            float e1 = __expf(lgt[h] - nm);
            s[h] = s[h] * e0 + e1;
            acc[h].x = acc[h].x * e0 + e1 * xl[h].x;
            acc[h].y = acc[h].y * e0 + e1 * xl[h].y;
            acc[h].z = acc[h].z * e0 + e1 * xl[h].z;
            acc[h].w = acc[h].w * e0 + e1 * xl[h].w;
            m[h] = nm;
        }
    }

    float4 o = make_float4(0.f, 0.f, 0.f, 0.f);
#pragma unroll
    for (int h = 0; h < 4; h++) {
        float r = 0.25f / s[h];
        o.x += acc[h].x * r; o.y += acc[h].y * r;
        o.z += acc[h].z * r; o.w += acc[h].w * r;
    }
    float4 gb = *(const float4*)&gat_b[lane * 4];
    o.x += gb.x; o.y += gb.y; o.z += gb.z; o.w += gb.w;

    float4 r4 = ln_compute(o, lg, lb, lane);
    *(float4*)&g_cat[(size_t)w * 256 + lane * 4] = r4;
}

// ---------------- residual LNs ------------------------------------------------------
__global__ void k_lnt1(const float* __restrict__ x,
                       const float* __restrict__ g, const float* __restrict__ b) {
    int row = (blockIdx.x * blockDim.x + threadIdx.x) >> 5;
    int lane = threadIdx.x & 31;
    if (row >= M_) return;
    float4 v  = *(const float4*)&x[(size_t)row * D_ + lane * 4];
    float4 v2 = *(const float4*)&g_oproj[(size_t)row * D_ + lane * 4];
    v.x += v2.x; v.y += v2.y; v.z += v2.z; v.w += v2.w;
    float4 r4 = ln_compute(v, g, b, lane);
    *(float4*)&g_x1[(size_t)row * D_ + lane * 4] = r4;
}

__global__ void k_lnt2(const float* __restrict__ g, const float* __restrict__ b) {
    int row = (blockIdx.x * blockDim.x + threadIdx.x) >> 5;
    int lane = threadIdx.x & 31;
    if (row >= M_) return;
    float4 v  = *(const float4*)&g_x1[(size_t)row * D_ + lane * 4];
    float4 v2 = *(const float4*)&g_f2[(size_t)row * D_ + lane * 4];
    v.x += v2.x; v.y += v2.y; v.z += v2.z; v.w += v2.w;
    float4 r4 = ln_compute(v, g, b, lane);
    *(float4*)&g_cat[(size_t)row * 256 + 128 + lane * 4] = r4;
}

__global__ void k_final(const float* __restrict__ x,
                        const float* __restrict__ g, const float* __restrict__ b,
                        float* __restrict__ out) {
    int row = (blockIdx.x * blockDim.x + threadIdx.x) >> 5;
    int lane = threadIdx.x & 31;
    if (row >= M_) return;
    float4 xsp = *(const float4*)&g_cat[(size_t)row * 256 + lane * 4];
    float4 xtp = *(const float4*)&g_cat[(size_t)row * 256 + 128 + lane * 4];
    float4 gt  = *(const float4*)&g_gate[(size_t)row * D_ + lane * 4];
    float4 xv  = *(const float4*)&x[(size_t)row * D_ + lane * 4];
    float4 v = make_float4(gt.x * xsp.x + (1.f - gt.x) * xtp.x + xv.x,
                           gt.y * xsp.y + (1.f - gt.y) * xtp.y + xv.y,
                           gt.z * xsp.z + (1.f - gt.z) * xtp.z + xv.z,
                           gt.w * xsp.w + (1.f - gt.w) * xtp.w + xv.w);
    float4 r4 = ln_compute(v, g, b, lane);
    *(float4*)&out[(size_t)row * D_ + lane * 4] = r4;
}

// ---------------- temporal attention ------------------------------------------------
__global__ void k_attn() {
    int w = blockIdx.x * 4 + (threadIdx.x >> 5);
    int lane = threadIdx.x & 31;
    if (w >= (B_ * N_) * H_) return;
    int bn = w >> 2;
    int h = w & 3;
    float q[8], k[8], v[8];
#pragma unroll
    for (int t = 0; t < 8; t++) {
        size_t base = ((size_t)bn * 8 + t) * 384 + h * 32 + lane;
        q[t] = g_qkv[base];
        k[t] = g_qkv[base + 128];
        v[t] = g_qkv[base + 256];
    }
    const float scale = 0.17677669529663687f;
#pragma unroll
    for (int t = 0; t < 8; t++) {
        float sc[8];
#pragma unroll
        for (int s = 0; s < 8; s++) sc[s] = warp_sum(q[t] * k[s]) * scale;
        float mx = sc[0];
#pragma unroll
        for (int s = 1; s < 8; s++) mx = fmaxf(mx, sc[s]);
        float den = 0.f;
#pragma unroll
        for (int s = 0; s < 8; s++) { sc[s] = __expf(sc[s] - mx); den += sc[s]; }
        float inv = 1.f / den;
        float o = 0.f;
#pragma unroll
        for (int s = 0; s < 8; s++) o += sc[s] * v[s];
        g_attno[((size_t)bn * 8 + t) * D_ + h * 32 + lane] = o * inv;
    }
}

// ---------------- launch ---------------------------------------------------------------
extern "C" void kernel_launch(void* const* d_in, const int* in_sizes, int n_in,
                              void* d_out, int out_size) {
    const float* x      = (const float*)d_in[0];
    const int*   edges  = (const int*)  d_in[1];
    const float* gat_att= (const float*)d_in[4];
    const float* gat_b  = (const float*)d_in[5];
    const float* in_b   = (const float*)d_in[7];
    const float* out_b  = (const float*)d_in[9];
    const float* ffn_b1 = (const float*)d_in[11];
    const float* ffn_b2 = (const float*)d_in[13];
    const float* fus_b  = (const float*)d_in[15];
    const float* lns_g  = (const float*)d_in[16];
    const float* lns_b  = (const float*)d_in[17];
    const float* lnt1_g = (const float*)d_in[18];
    const float* lnt1_b = (const float*)d_in[19];
    const float* lnt2_g = (const float*)d_in[20];
    const float* lnt2_b = (const float*)d_in[21];
    const float* lnf_g  = (const float*)d_in[22];
    const float* lnf_b  = (const float*)d_in[23];
    float* out = (float*)d_out;

    float *p_xlr, *p_qkv, *p_attno, *p_oproj, *p_x1, *p_hid, *p_f2, *p_cat, *p_gate;
    float *p_bxq, *p_Bxq, *p_Bout, *p_Bffn1, *p_Bffn2, *p_Bfus;
    cudaGetSymbolAddress((void**)&p_xlr,   g_xlr);
    cudaGetSymbolAddress((void**)&p_qkv,   g_qkv);
    cudaGetSymbolAddress((void**)&p_attno, g_attno);
    cudaGetSymbolAddress((void**)&p_oproj, g_oproj);
    cudaGetSymbolAddress((void**)&p_x1,    g_x1);
    cudaGetSymbolAddress((void**)&p_hid,   g_hid);
    cudaGetSymbolAddress((void**)&p_f2,    g_f2);
    cudaGetSymbolAddress((void**)&p_cat,   g_cat);
    cudaGetSymbolAddress((void**)&p_gate,  g_gate);
    cudaGetSymbolAddress((void**)&p_bxq,   g_bias_xq);
    cudaGetSymbolAddress((void**)&p_Bxq,   g_Bxq);
    cudaGetSymbolAddress((void**)&p_Bout,  g_Bout);
    cudaGetSymbolAddress((void**)&p_Bffn1, g_Bffn1);
    cudaGetSymbolAddress((void**)&p_Bffn2, g_Bffn2);
    cudaGetSymbolAddress((void**)&p_Bfus,  g_Bfus);

    cudaFuncSetAttribute(hgemm, cudaFuncAttributeMaxDynamicSharedMemorySize, SMEMSZ);

    // side stream + fork/join events (created once, outside capture: the
    // harness's first call is the uncaptured correctness run)
    static cudaStream_t s1 = nullptr;
    static cudaEvent_t evFork = nullptr, evJoin = nullptr;
    if (s1 == nullptr) {
        cudaStreamCreateWithFlags(&s1, cudaStreamNonBlocking);
        cudaEventCreateWithFlags(&evFork, cudaEventDisableTiming);
        cudaEventCreateWithFlags(&evJoin, cudaEventDisableTiming);
    }

    // prep
    k_init0<<<6, 256>>>(in_b);
    k_scatter<<<E_ / 256, 256>>>(edges);
    k_packw<<<dim3(256, 7), 256>>>((const float*)d_in[2], (const float*)d_in[3],
                                   (const float*)d_in[6], (const float*)d_in[8],
                                   (const float*)d_in[10], (const float*)d_in[12],
                                   (const float*)d_in[14]);

    // merged spatial+qkv: [xlr | qkv] = x @ [Wl|Wr|Wqkv]
    hgemm<<<dim3(11, 256), 256, SMEMSZ>>>(x, p_Bxq, p_bxq,
                                          p_xlr, 1024, 1024, p_qkv, 384, 128, 1);

    // fork: GAT branch runs on s1 concurrently with the temporal chain
    cudaEventRecord(evFork, 0);
    cudaStreamWaitEvent(s1, evFork, 0);
    k_gat<<<M_ / 8, 256, 0, s1>>>(gat_att, gat_b, lns_g, lns_b);
    cudaEventRecord(evJoin, s1);

    // temporal branch (default stream)
    k_attn<<<(B_ * N_ * H_) / 4, 128>>>();
    hgemm<<<dim3(1, 256), 256, SMEMSZ>>>(p_attno, p_Bout, out_b,
                                         p_oproj, 128, 128, p_oproj, 128, 128, 1);
    k_lnt1<<<M_ / 8, 256>>>(x, lnt1_g, lnt1_b);
    hgemm<<<dim3(4, 256), 256, SMEMSZ>>>(p_x1, p_Bffn1, ffn_b1,
                                         p_hid, 512, 512, p_hid, 512, 128, 2);
    hgemm<<<dim3(1, 256), 256, SMEMSZ>>>(p_hid, p_Bffn2, ffn_b2,
                                         p_f2, 128, 128, p_f2, 128, 512, 1);
    k_lnt2<<<M_ / 8, 256>>>(lnt2_g, lnt2_b);

    // join: fusion needs g_cat[:, :128] from the GAT branch
    cudaStreamWaitEvent(0, evJoin, 0);
    hgemm<<<dim3(1, 256), 256, SMEMSZ>>>(p_cat, p_Bfus, fus_b,
                                         p_gate, 128, 128, p_gate, 128, 256, 3);
    k_final<<<M_ / 8, 256>>>(x, lnf_g, lnf_b, out);
}

// round 11
// speedup vs baseline: 1.1594x; 1.0403x over previous
#include <cuda_runtime.h>
#include <cuda_bf16.h>
#include <math.h>
#include <stdint.h>

#define B_  2
#define N_  1024
#define T_  8
#define D_  128
#define H_  4
#define E_  8192
#define M_  16384
#define MAXDEG 128

// ---------------- scratch (device globals) ----------------------------------
__device__ __align__(256) float g_xlr[(size_t)M_ * 1024];   // [xl(512)|xr(512)]
__device__ __align__(256) float g_qkv[(size_t)M_ * 384];
__device__ __align__(256) float g_attno[(size_t)M_ * 128];
__device__ __align__(256) float g_oproj[(size_t)M_ * 128];
__device__ __align__(256) float g_x1[(size_t)M_ * 128];
__device__ __align__(256) float g_hid[(size_t)M_ * 512];
__device__ __align__(256) float g_f2[(size_t)M_ * 128];
__device__ __align__(256) float g_cat[(size_t)M_ * 256];    // [x_sp | x_tp]
__device__ __align__(256) float g_gate[(size_t)M_ * 128];
// packed tf32 weights, [n][k] layout (pre-rounded via cvt.rna)
__device__ __align__(256) float g_Bxq[1408 * 128];          // [Wl|Wr|Wqkv]
__device__ __align__(256) float g_bias_xq[1408];
__device__ __align__(256) float g_Bout[128 * 128];
__device__ __align__(256) float g_Bffn1[512 * 128];
__device__ __align__(256) float g_Bffn2[128 * 512];
__device__ __align__(256) float g_Bfus[128 * 256];
// CSR
__device__ int g_deg[N_];
__device__ int g_csr[N_ * MAXDEG];

// ---------------- helpers ------------------------------------------------------
__device__ __forceinline__ float warp_sum(float v) {
#pragma unroll
    for (int o = 16; o; o >>= 1) v += __shfl_xor_sync(0xFFFFFFFFu, v, o);
    return v;
}
__device__ __forceinline__ uint32_t smem_u32(const void* p) {
    uint32_t a;
    asm("{ .reg .u64 t; cvta.to.shared.u64 t, %1; cvt.u32.u64 %0, t; }"
        : "=r"(a) : "l"(p));
    return a;
}
#define CP16(dst, src) \
    asm volatile("cp.async.cg.shared.global [%0], [%1], 16;" :: "r"(dst), "l"(src))
#define CVT_TF32(u, f) asm("cvt.rna.tf32.f32 %0, %1;" : "=r"(u) : "f"(f))

__device__ __forceinline__ void mma_tf32(float c[4], const uint32_t a[4],
                                         const uint32_t b[2]) {
    asm volatile(
        "mma.sync.aligned.m16n8k8.row.col.f32.tf32.tf32.f32 "
        "{%0,%1,%2,%3}, {%4,%5,%6,%7}, {%8,%9}, {%0,%1,%2,%3};"
        : "+f"(c[0]), "+f"(c[1]), "+f"(c[2]), "+f"(c[3])
        : "r"(a[0]), "r"(a[1]), "r"(a[2]), "r"(a[3]), "r"(b[0]), "r"(b[1]));
}

// ---------------- init + CSR + bias_xq -------------------------------------------
__global__ void k_bias(const float* __restrict__ in_b) {
    int i = blockIdx.x * blockDim.x + threadIdx.x;
    if (i < 1408) g_bias_xq[i] = (i < 1024) ? 0.f : in_b[i - 1024];
}
__global__ void k_csr0() {
    int i = blockIdx.x * blockDim.x + threadIdx.x;
    if (i < N_) { g_deg[i] = 1; g_csr[i * MAXDEG] = i; }   // self loop
}
__global__ void k_scatter(const int* __restrict__ edges) {
    int e = blockIdx.x * blockDim.x + threadIdx.x;
    if (e >= E_) return;
    int s = edges[e], d = edges[E_ + e];
    int pos = atomicAdd(&g_deg[d], 1);
    if (pos < MAXDEG) g_csr[d * MAXDEG + pos] = s;
}

// ---------------- weight packing: transpose to [n][k], round to tf32 -------------
__global__ void k_packw(const float* wl, const float* wr, const float* inw,
                        const float* outw, const float* f1w, const float* f2w,
                        const float* fw) {
    int job = blockIdx.y;
    int idx = blockIdx.x * 256 + threadIdx.x;
    const float* W; float* Bo; int K, Nw, coff = 0;
    switch (job) {
        case 0: W = wl;   Bo = g_Bxq;   K = 128; Nw = 512; break;
        case 1: W = wr;   Bo = g_Bxq;   K = 128; Nw = 512; coff = 512; break;
        case 2: W = inw;  Bo = g_Bxq;   K = 128; Nw = 384; coff = 1024; break;
        case 3: W = outw; Bo = g_Bout;  K = 128; Nw = 128; break;
        case 4: W = f1w;  Bo = g_Bffn1; K = 128; Nw = 512; break;
        case 5: W = f2w;  Bo = g_Bffn2; K = 512; Nw = 128; break;
        default:W = fw;   Bo = g_Bfus;  K = 256; Nw = 128; break;
    }
    if (idx >= K * Nw) return;
    int k = idx / Nw, n = idx % Nw;
    uint32_t u;
    CVT_TF32(u, W[idx]);
    Bo[(size_t)(coff + n) * K + k] = __uint_as_float(u);
}

// ---------------- tf32 mma.sync GEMM (256thr, target 3 CTA/SM) --------------------
#define KP 20
#define APLANE (64 * KP)
#define BPLANE (128 * KP)
#define SMEMSZ ((APLANE + BPLANE) * 3 * 4)

__global__ void __launch_bounds__(256, 3) hgemm(
        const float* __restrict__ A, const float* __restrict__ Bp,
        const float* __restrict__ bias,
        float* __restrict__ C1, int N1, int s1,
        float* __restrict__ C2, int s2,
        int K, int mode) {
    extern __shared__ float sm[];
    float* sA = sm;                    // [3][64][KP]
    float* sB = sm + 3 * APLANE;       // [3][128][KP]
    int tid = threadIdx.x, wid = tid >> 5, lane = tid & 31;
    int wm = wid >> 2, wn = wid & 3;
    int rowBase = blockIdx.y * 64, colBase = blockIdx.x * 128;
    int nk = K >> 4;

    float acc[2][4][4];
#pragma unroll
    for (int i = 0; i < 2; i++)
#pragma unroll
        for (int j = 0; j < 4; j++)
#pragma unroll
            for (int q = 0; q < 4; q++) acc[i][j][q] = 0.f;

    int ar = tid >> 2, aq = tid & 3;
    int br = tid >> 1, bq = (tid & 1) * 2;
    const char* Asrc = (const char*)(A + (size_t)(rowBase + ar) * K + aq * 4);
    const char* Bsrc = (const char*)(Bp + (size_t)(colBase + br) * K + bq * 4);
    uint32_t dA = smem_u32(sA) + (uint32_t)(ar * KP + aq * 4) * 4;
    uint32_t dB = smem_u32(sB) + (uint32_t)(br * KP + bq * 4) * 4;

    auto ld = [&](int kt, int buf) {
        CP16(dA + buf * (APLANE * 4), Asrc + (size_t)kt * 64);
        CP16(dB + buf * (BPLANE * 4), Bsrc + (size_t)kt * 64);
        CP16(dB + buf * (BPLANE * 4) + 16, Bsrc + (size_t)kt * 64 + 16);
        asm volatile("cp.async.commit_group;" ::: "memory");
    };

    ld(0, 0);
    if (nk > 1) ld(1, 1);

    int fr = lane >> 2, fq = lane & 3;
    const float* awp = sA + (wm * 32 + fr) * KP + fq;
    const float* bwp = sB + (wn * 32 + fr) * KP + fq;

    for (int kt = 0; kt < nk; kt++) {
        int buf = kt % 3;
        if (kt + 1 < nk) asm volatile("cp.async.wait_group 1;" ::: "memory");
        else             asm volatile("cp.async.wait_group 0;" ::: "memory");
        __syncthreads();
        if (kt + 2 < nk) ld(kt + 2, (kt + 2) % 3);

        const float* aw = awp + buf * APLANE;
        const float* bw = bwp + buf * BPLANE;
#pragma unroll
        for (int k8 = 0; k8 < 2; k8++) {
            uint32_t ua[2][4], ub[4][2];
#pragma unroll
            for (int mi = 0; mi < 2; mi++) {
                const float* ap = aw + mi * (16 * KP) + k8 * 8;
                CVT_TF32(ua[mi][0], ap[0]);
                CVT_TF32(ua[mi][1], ap[8 * KP]);
                CVT_TF32(ua[mi][2], ap[4]);
                CVT_TF32(ua[mi][3], ap[8 * KP + 4]);
            }
#pragma unroll
            for (int ni = 0; ni < 4; ni++) {
                const float* bp = bw + ni * (8 * KP) + k8 * 8;
                ub[ni][0] = __float_as_uint(bp[0]);
                ub[ni][1] = __float_as_uint(bp[4]);
            }
#pragma unroll
            for (int mi = 0; mi < 2; mi++)
#pragma unroll
                for (int ni = 0; ni < 4; ni++)
                    mma_tf32(acc[mi][ni], ua[mi], ub[ni]);
        }
    }

    // ---- epilogue ----
    int fc2 = (lane & 3) * 2;
#pragma unroll
    for (int mi = 0; mi < 2; mi++) {
        int r0 = rowBase + wm * 32 + mi * 16 + fr;
#pragma unroll
        for (int ni = 0; ni < 4; ni++) {
            int col = colBase + wn * 32 + ni * 8 + fc2;
            float b0 = bias[col], b1 = bias[col + 1];
            float v[4] = {acc[mi][ni][0] + b0, acc[mi][ni][1] + b1,
                          acc[mi][ni][2] + b0, acc[mi][ni][3] + b1};
            if (mode == 2) {
#pragma unroll
                for (int q = 0; q < 4; q++)
                    v[q] = 0.5f * v[q] * (1.f + erff(v[q] * 0.70710678118654752f));
            } else if (mode == 3) {
#pragma unroll
                for (int q = 0; q < 4; q++) v[q] = 1.f / (1.f + __expf(-v[q]));
            }
            if (col < N1) {
                *(float2*)&C1[(size_t)r0 * s1 + col]       = make_float2(v[0], v[1]);
                *(float2*)&C1[(size_t)(r0 + 8) * s1 + col] = make_float2(v[2], v[3]);
            } else {
                int c2 = col - N1;
                *(float2*)&C2[(size_t)r0 * s2 + c2]        = make_float2(v[0], v[1]);
                *(float2*)&C2[(size_t)(r0 + 8) * s2 + c2]  = make_float2(v[2], v[3]);
            }
        }
    }
}

// ---------------- LayerNorm compute ---------------------------------------------
__device__ __forceinline__ float4 ln_compute(float4 v, const float* g, const float* b,
                                             int lane) {
    float mean = warp_sum(v.x + v.y + v.z + v.w) * (1.f / 128.f);
    float4 c = make_float4(v.x - mean, v.y - mean, v.z - mean, v.w - mean);
    float var = warp_sum(c.x * c.x + c.y * c.y + c.z * c.z + c.w * c.w) * (1.f / 128.f);
    float rs = rsqrtf(var + 1e-5f);
    float4 gv = *(const float4*)&g[lane * 4];
    float4 bv = *(const float4*)&b[lane * 4];
    return make_float4(c.x * rs * gv.x + bv.x, c.y * rs * gv.y + bv.y,
                       c.z * rs * gv.z + bv.z, c.w * rs * gv.w + bv.w);
}

// ---------------- fused GAT (online softmax, dst-centric) --------------------------
__global__ void k_gat(const float* __restrict__ att, const float* __restrict__ gat_b,
                      const float* __restrict__ lg, const float* __restrict__ lb) {
    int w = (blockIdx.x * blockDim.x + threadIdx.x) >> 5;   // row = (b*N+n)*T+t
    int lane = threadIdx.x & 31;
    if (w >= M_) return;
    int bn = w >> 3;
    int n = bn & (N_ - 1);
    int b = bn >> 10;
    int t = w & 7;

    const float4* xr4 = (const float4*)(g_xlr + (size_t)w * 1024 + 512);
    float4 xr[4], av[4];
#pragma unroll
    for (int h = 0; h < 4; h++) {
        xr[h] = xr4[h * 32 + lane];
        av[h] = ((const float4*)att)[h * 32 + lane];
    }
    float4 acc[4];
#pragma unroll
    for (int h = 0; h < 4; h++) acc[h] = make_float4(0.f, 0.f, 0.f, 0.f);
    float m[4] = {-INFINITY, -INFINITY, -INFINITY, -INFINITY};
    float s[4] = {0.f, 0.f, 0.f, 0.f};

    int deg = g_deg[n];
    if (deg > MAXDEG) deg = MAXDEG;
    const int* clist = g_csr + n * MAXDEG;

    for (int i = 0; i < deg; i++) {
        int src = clist[i];
        const float4* xl4 = (const float4*)(g_xlr + ((size_t)((b * N_ + src) * T_ + t)) * 1024);
        float4 xl[4];
        float lgt[4];
#pragma unroll
        for (int h = 0; h < 4; h++) {
            float4 a = xl4[h * 32 + lane];
            xl[h] = a;
            float v0 = a.x + xr[h].x; v0 = v0 > 0.f ? v0 : 0.2f * v0;
            float v1 = a.y + xr[h].y; v1 = v1 > 0.f ? v1 : 0.2f * v1;
            float v2 = a.z + xr[h].z; v2 = v2 > 0.f ? v2 : 0.2f * v2;
            float v3 = a.w + xr[h].w; v3 = v3 > 0.f ? v3 : 0.2f * v3;
            lgt[h] = warp_sum(av[h].x * v0 + av[h].y * v1 + av[h].z * v2 + av[h].w * v3);
        }
#pragma unroll
        for (int h = 0; h < 4; h++) {
            float nm = fmaxf(m[h], lgt[h]);
            float e0 = __expf(m[h] - nm);
            float e1 = __expf(lgt[h] - nm);
            s[h] = s[h] * e0 + e1;
            acc[h].x = acc[h].x * e0 + e1 * xl[h].x;
            acc[h].y = acc[h].y * e0 + e1 * xl[h].y;
            acc[h].z = acc[h].z * e0 + e1 * xl[h].z;
            acc[h].w = acc[h].w * e0 + e1 * xl[h].w;
            m[h] = nm;
        }
    }

    float4 o = make_float4(0.f, 0.f, 0.f, 0.f);
#pragma unroll
    for (int h = 0; h < 4; h++) {
        float r = 0.25f / s[h];
        o.x += acc[h].x * r; o.y += acc[h].y * r;
        o.z += acc[h].z * r; o.w += acc[h].w * r;
    }
    float4 gb = *(const float4*)&gat_b[lane * 4];
    o.x += gb.x; o.y += gb.y; o.z += gb.z; o.w += gb.w;

    float4 r4 = ln_compute(o, lg, lb, lane);
    *(float4*)&g_cat[(size_t)w * 256 + lane * 4] = r4;
}

// ---------------- residual LNs ------------------------------------------------------
__global__ void k_lnt1(const float* __restrict__ x,
                       const float* __restrict__ g, const float* __restrict__ b) {
    int row = (blockIdx.x * blockDim.x + threadIdx.x) >> 5;
    int lane = threadIdx.x & 31;
    if (row >= M_) return;
    float4 v  = *(const float4*)&x[(size_t)row * D_ + lane * 4];
    float4 v2 = *(const float4*)&g_oproj[(size_t)row * D_ + lane * 4];
    v.x += v2.x; v.y += v2.y; v.z += v2.z; v.w += v2.w;
    float4 r4 = ln_compute(v, g, b, lane);
    *(float4*)&g_x1[(size_t)row * D_ + lane * 4] = r4;
}

__global__ void k_lnt2(const float* __restrict__ g, const float* __restrict__ b) {
    int row = (blockIdx.x * blockDim.x + threadIdx.x) >> 5;
    int lane = threadIdx.x & 31;
    if (row >= M_) return;
    float4 v  = *(const float4*)&g_x1[(size_t)row * D_ + lane * 4];
    float4 v2 = *(const float4*)&g_f2[(size_t)row * D_ + lane * 4];
    v.x += v2.x; v.y += v2.y; v.z += v2.z; v.w += v2.w;
    float4 r4 = ln_compute(v, g, b, lane);
    *(float4*)&g_cat[(size_t)row * 256 + 128 + lane * 4] = r4;
}

__global__ void k_final(const float* __restrict__ x,
                        const float* __restrict__ g, const float* __restrict__ b,
                        float* __restrict__ out) {
    int row = (blockIdx.x * blockDim.x + threadIdx.x) >> 5;
    int lane = threadIdx.x & 31;
    if (row >= M_) return;
    float4 xsp = *(const float4*)&g_cat[(size_t)row * 256 + lane * 4];
    float4 xtp = *(const float4*)&g_cat[(size_t)row * 256 + 128 + lane * 4];
    float4 gt  = *(const float4*)&g_gate[(size_t)row * D_ + lane * 4];
    float4 xv  = *(const float4*)&x[(size_t)row * D_ + lane * 4];
    float4 v = make_float4(gt.x * xsp.x + (1.f - gt.x) * xtp.x + xv.x,
                           gt.y * xsp.y + (1.f - gt.y) * xtp.y + xv.y,
                           gt.z * xsp.z + (1.f - gt.z) * xtp.z + xv.z,
                           gt.w * xsp.w + (1.f - gt.w) * xtp.w + xv.w);
    float4 r4 = ln_compute(v, g, b, lane);
    *(float4*)&out[(size_t)row * D_ + lane * 4] = r4;
}

// ---------------- temporal attention ------------------------------------------------
__global__ void k_attn() {
    int w = blockIdx.x * 4 + (threadIdx.x >> 5);
    int lane = threadIdx.x & 31;
    if (w >= (B_ * N_) * H_) return;
    int bn = w >> 2;
    int h = w & 3;
    float q[8], k[8], v[8];
#pragma unroll
    for (int t = 0; t < 8; t++) {
        size_t base = ((size_t)bn * 8 + t) * 384 + h * 32 + lane;
        q[t] = g_qkv[base];
        k[t] = g_qkv[base + 128];
        v[t] = g_qkv[base + 256];
    }
    const float scale = 0.17677669529663687f;
#pragma unroll
    for (int t = 0; t < 8; t++) {
        float sc[8];
#pragma unroll
        for (int s = 0; s < 8; s++) sc[s] = warp_sum(q[t] * k[s]) * scale;
        float mx = sc[0];
#pragma unroll
        for (int s = 1; s < 8; s++) mx = fmaxf(mx, sc[s]);
        float den = 0.f;
#pragma unroll
        for (int s = 0; s < 8; s++) { sc[s] = __expf(sc[s] - mx); den += sc[s]; }
        float inv = 1.f / den;
        float o = 0.f;
#pragma unroll
        for (int s = 0; s < 8; s++) o += sc[s] * v[s];
        g_attno[((size_t)bn * 8 + t) * D_ + h * 32 + lane] = o * inv;
    }
}

// ---------------- launch ---------------------------------------------------------------
extern "C" void kernel_launch(void* const* d_in, const int* in_sizes, int n_in,
                              void* d_out, int out_size) {
    const float* x      = (const float*)d_in[0];
    const int*   edges  = (const int*)  d_in[1];
    const float* gat_att= (const float*)d_in[4];
    const float* gat_b  = (const float*)d_in[5];
    const float* in_b   = (const float*)d_in[7];
    const float* out_b  = (const float*)d_in[9];
    const float* ffn_b1 = (const float*)d_in[11];
    const float* ffn_b2 = (const float*)d_in[13];
    const float* fus_b  = (const float*)d_in[15];
    const float* lns_g  = (const float*)d_in[16];
    const float* lns_b  = (const float*)d_in[17];
    const float* lnt1_g = (const float*)d_in[18];
    const float* lnt1_b = (const float*)d_in[19];
    const float* lnt2_g = (const float*)d_in[20];
    const float* lnt2_b = (const float*)d_in[21];
    const float* lnf_g  = (const float*)d_in[22];
    const float* lnf_b  = (const float*)d_in[23];
    float* out = (float*)d_out;

    float *p_xlr, *p_qkv, *p_attno, *p_oproj, *p_x1, *p_hid, *p_f2, *p_cat, *p_gate;
    float *p_bxq, *p_Bxq, *p_Bout, *p_Bffn1, *p_Bffn2, *p_Bfus;
    cudaGetSymbolAddress((void**)&p_xlr,   g_xlr);
    cudaGetSymbolAddress((void**)&p_qkv,   g_qkv);
    cudaGetSymbolAddress((void**)&p_attno, g_attno);
    cudaGetSymbolAddress((void**)&p_oproj, g_oproj);
    cudaGetSymbolAddress((void**)&p_x1,    g_x1);
    cudaGetSymbolAddress((void**)&p_hid,   g_hid);
    cudaGetSymbolAddress((void**)&p_f2,    g_f2);
    cudaGetSymbolAddress((void**)&p_cat,   g_cat);
    cudaGetSymbolAddress((void**)&p_gate,  g_gate);
    cudaGetSymbolAddress((void**)&p_bxq,   g_bias_xq);
    cudaGetSymbolAddress((void**)&p_Bxq,   g_Bxq);
    cudaGetSymbolAddress((void**)&p_Bout,  g_Bout);
    cudaGetSymbolAddress((void**)&p_Bffn1, g_Bffn1);
    cudaGetSymbolAddress((void**)&p_Bffn2, g_Bffn2);
    cudaGetSymbolAddress((void**)&p_Bfus,  g_Bfus);

    cudaFuncSetAttribute(hgemm, cudaFuncAttributeMaxDynamicSharedMemorySize, SMEMSZ);

    static cudaStream_t s1 = nullptr;
    static cudaEvent_t evFork = nullptr, evJoin = nullptr;
    if (s1 == nullptr) {
        cudaStreamCreateWithFlags(&s1, cudaStreamNonBlocking);
        cudaEventCreateWithFlags(&evFork, cudaEventDisableTiming);
        cudaEventCreateWithFlags(&evJoin, cudaEventDisableTiming);
    }

    // prep: CSR build on s1 (only k_gat needs it); bias+packw on main
    k_csr0<<<4, 256, 0, s1>>>();
    k_scatter<<<E_ / 256, 256, 0, s1>>>(edges);
    k_bias<<<6, 256>>>(in_b);
    k_packw<<<dim3(256, 7), 256>>>((const float*)d_in[2], (const float*)d_in[3],
                                   (const float*)d_in[6], (const float*)d_in[8],
                                   (const float*)d_in[10], (const float*)d_in[12],
                                   (const float*)d_in[14]);

    // merged spatial+qkv: [xlr | qkv] = x @ [Wl|Wr|Wqkv]
    hgemm<<<dim3(11, 256), 256, SMEMSZ>>>(x, p_Bxq, p_bxq,
                                          p_xlr, 1024, 1024, p_qkv, 384, 128, 1);

    // fork: GAT branch on s1 (CSR already resident there)
    cudaEventRecord(evFork, 0);
    cudaStreamWaitEvent(s1, evFork, 0);
    k_gat<<<M_ / 8, 256, 0, s1>>>(gat_att, gat_b, lns_g, lns_b);
    cudaEventRecord(evJoin, s1);

    // temporal branch (default stream)
    k_attn<<<(B_ * N_ * H_) / 4, 128>>>();
    hgemm<<<dim3(1, 256), 256, SMEMSZ>>>(p_attno, p_Bout, out_b,
                                         p_oproj, 128, 128, p_oproj, 128, 128, 1);
    k_lnt1<<<M_ / 8, 256>>>(x, lnt1_g, lnt1_b);
    hgemm<<<dim3(4, 256), 256, SMEMSZ>>>(p_x1, p_Bffn1, ffn_b1,
                                         p_hid, 512, 512, p_hid, 512, 128, 2);
    hgemm<<<dim3(1, 256), 256, SMEMSZ>>>(p_hid, p_Bffn2, ffn_b2,
                                         p_f2, 128, 128, p_f2, 128, 512, 1);
    k_lnt2<<<M_ / 8, 256>>>(lnt2_g, lnt2_b);

    // join: fusion needs g_cat[:, :128] from the GAT branch
    cudaStreamWaitEvent(0, evJoin, 0);
    hgemm<<<dim3(1, 256), 256, SMEMSZ>>>(p_cat, p_Bfus, fus_b,
                                         p_gate, 128, 128, p_gate, 128, 256, 3);
    k_final<<<M_ / 8, 256>>>(x, lnf_g, lnf_b, out);
}

// round 12
// speedup vs baseline: 1.1856x; 1.0226x over previous
#include <cuda_runtime.h>
#include <cuda_bf16.h>
#include <math.h>
#include <stdint.h>

#define B_  2
#define N_  1024
#define T_  8
#define D_  128
#define H_  4
#define E_  8192
#define M_  16384
#define MAXDEG 128

// ---------------- scratch (device globals) ----------------------------------
__device__ __align__(256) float g_xlr[(size_t)M_ * 1024];   // [xl(512)|xr(512)]
__device__ __align__(256) float g_qkv[(size_t)M_ * 384];
__device__ __align__(256) float g_attno[(size_t)M_ * 128];
__device__ __align__(256) float g_x1[(size_t)M_ * 128];
__device__ __align__(256) float g_hid[(size_t)M_ * 512];
__device__ __align__(256) float g_cat[(size_t)M_ * 256];    // [x_sp | x_tp]
// packed tf32 weights, [n][k] layout (pre-rounded via cvt.rna)
__device__ __align__(256) float g_Bxq[1408 * 128];          // [Wl|Wr|Wqkv]
__device__ __align__(256) float g_bias_xq[1408];
__device__ __align__(256) float g_Bout[128 * 128];
__device__ __align__(256) float g_Bffn1[512 * 128];
__device__ __align__(256) float g_Bffn2[128 * 512];
__device__ __align__(256) float g_Bfus[128 * 256];
// CSR
__device__ int g_deg[N_];
__device__ int g_csr[N_ * MAXDEG];

// ---------------- helpers ------------------------------------------------------
__device__ __forceinline__ float warp_sum(float v) {
#pragma unroll
    for (int o = 16; o; o >>= 1) v += __shfl_xor_sync(0xFFFFFFFFu, v, o);
    return v;
}
__device__ __forceinline__ uint32_t smem_u32(const void* p) {
    uint32_t a;
    asm("{ .reg .u64 t; cvta.to.shared.u64 t, %1; cvt.u32.u64 %0, t; }"
        : "=r"(a) : "l"(p));
    return a;
}
#define CP16(dst, src) \
    asm volatile("cp.async.cg.shared.global [%0], [%1], 16;" :: "r"(dst), "l"(src))
#define CVT_TF32(u, f) asm("cvt.rna.tf32.f32 %0, %1;" : "=r"(u) : "f"(f))

__device__ __forceinline__ void mma_tf32(float c[4], const uint32_t a[4],
                                         const uint32_t b[2]) {
    asm volatile(
        "mma.sync.aligned.m16n8k8.row.col.f32.tf32.tf32.f32 "
        "{%0,%1,%2,%3}, {%4,%5,%6,%7}, {%8,%9}, {%0,%1,%2,%3};"
        : "+f"(c[0]), "+f"(c[1]), "+f"(c[2]), "+f"(c[3])
        : "r"(a[0]), "r"(a[1]), "r"(a[2]), "r"(a[3]), "r"(b[0]), "r"(b[1]));
}

__device__ __forceinline__ float4 ln_compute(float4 v, const float* g, const float* b,
                                             int lane) {
    float mean = warp_sum(v.x + v.y + v.z + v.w) * (1.f / 128.f);
    float4 c = make_float4(v.x - mean, v.y - mean, v.z - mean, v.w - mean);
    float var = warp_sum(c.x * c.x + c.y * c.y + c.z * c.z + c.w * c.w) * (1.f / 128.f);
    float rs = rsqrtf(var + 1e-5f);
    float4 gv = *(const float4*)&g[lane * 4];
    float4 bv = *(const float4*)&b[lane * 4];
    return make_float4(c.x * rs * gv.x + bv.x, c.y * rs * gv.y + bv.y,
                       c.z * rs * gv.z + bv.z, c.w * rs * gv.w + bv.w);
}

// ---------------- init + CSR + bias_xq -------------------------------------------
__global__ void k_bias(const float* __restrict__ in_b) {
    int i = blockIdx.x * blockDim.x + threadIdx.x;
    if (i < 1408) g_bias_xq[i] = (i < 1024) ? 0.f : in_b[i - 1024];
}
__global__ void k_csr0() {
    int i = blockIdx.x * blockDim.x + threadIdx.x;
    if (i < N_) { g_deg[i] = 1; g_csr[i * MAXDEG] = i; }   // self loop
}
__global__ void k_scatter(const int* __restrict__ edges) {
    int e = blockIdx.x * blockDim.x + threadIdx.x;
    if (e >= E_) return;
    int s = edges[e], d = edges[E_ + e];
    int pos = atomicAdd(&g_deg[d], 1);
    if (pos < MAXDEG) g_csr[d * MAXDEG + pos] = s;
}

// ---------------- weight packing -----------------------------------------------
__global__ void k_packw(const float* wl, const float* wr, const float* inw,
                        const float* outw, const float* f1w, const float* f2w,
                        const float* fw) {
    int job = blockIdx.y;
    int idx = blockIdx.x * 256 + threadIdx.x;
    const float* W; float* Bo; int K, Nw, coff = 0;
    switch (job) {
        case 0: W = wl;   Bo = g_Bxq;   K = 128; Nw = 512; break;
        case 1: W = wr;   Bo = g_Bxq;   K = 128; Nw = 512; coff = 512; break;
        case 2: W = inw;  Bo = g_Bxq;   K = 128; Nw = 384; coff = 1024; break;
        case 3: W = outw; Bo = g_Bout;  K = 128; Nw = 128; break;
        case 4: W = f1w;  Bo = g_Bffn1; K = 128; Nw = 512; break;
        case 5: W = f2w;  Bo = g_Bffn2; K = 512; Nw = 128; break;
        default:W = fw;   Bo = g_Bfus;  K = 256; Nw = 128; break;
    }
    if (idx >= K * Nw) return;
    int k = idx / Nw, n = idx % Nw;
    uint32_t u;
    CVT_TF32(u, W[idx]);
    Bo[(size_t)(coff + n) * K + k] = __uint_as_float(u);
}

// ---------------- tf32 mma.sync GEMM, templated epilogue --------------------------
// MODE 1: +bias -> dual dest (col<N1 -> C1 stride s1, else C2 stride s2)
// MODE 2: +bias+GELU -> C1 (stride s1)
// MODE 4: +bias, LN(xres + C) -> C1 (stride 128)       [out-proj + lnt1]
// MODE 5: +bias, LN(xres + C) -> C1 (stride 256)       [ffn2 + lnt2 -> cat+128]
// MODE 6: +bias, sigmoid gate; xsp=C2[r*256], xtp=C2[r*256+128];
//         LN(g*xsp+(1-g)*xtp+xres) -> C1 (stride 128)  [fusion + final]
#define KP 20
#define APLANE (64 * KP)
#define BPLANE (128 * KP)
#define SMEMSZ ((APLANE + BPLANE) * 3 * 4)

template<int MODE>
__global__ void __launch_bounds__(256, 3) hgemm(
        const float* __restrict__ A, const float* __restrict__ Bp,
        const float* __restrict__ bias,
        float* __restrict__ C1, int N1, int s1,
        float* __restrict__ C2, int s2,
        int K,
        const float* __restrict__ xres,
        const float* __restrict__ lng, const float* __restrict__ lnb) {
    extern __shared__ float sm[];
    float* sA = sm;                    // [3][64][KP]
    float* sB = sm + 3 * APLANE;       // [3][128][KP]
    int tid = threadIdx.x, wid = tid >> 5, lane = tid & 31;
    int wm = wid >> 2, wn = wid & 3;
    int rowBase = blockIdx.y * 64, colBase = blockIdx.x * 128;
    int nk = K >> 4;

    float acc[2][4][4];
#pragma unroll
    for (int i = 0; i < 2; i++)
#pragma unroll
        for (int j = 0; j < 4; j++)
#pragma unroll
            for (int q = 0; q < 4; q++) acc[i][j][q] = 0.f;

    int ar = tid >> 2, aq = tid & 3;
    int br = tid >> 1, bq = (tid & 1) * 2;
    const char* Asrc = (const char*)(A + (size_t)(rowBase + ar) * K + aq * 4);
    const char* Bsrc = (const char*)(Bp + (size_t)(colBase + br) * K + bq * 4);
    uint32_t dA = smem_u32(sA) + (uint32_t)(ar * KP + aq * 4) * 4;
    uint32_t dB = smem_u32(sB) + (uint32_t)(br * KP + bq * 4) * 4;

    auto ld = [&](int kt, int buf) {
        CP16(dA + buf * (APLANE * 4), Asrc + (size_t)kt * 64);
        CP16(dB + buf * (BPLANE * 4), Bsrc + (size_t)kt * 64);
        CP16(dB + buf * (BPLANE * 4) + 16, Bsrc + (size_t)kt * 64 + 16);
        asm volatile("cp.async.commit_group;" ::: "memory");
    };

    ld(0, 0);
    if (nk > 1) ld(1, 1);

    int fr = lane >> 2, fq = lane & 3;
    const float* awp = sA + (wm * 32 + fr) * KP + fq;
    const float* bwp = sB + (wn * 32 + fr) * KP + fq;

    for (int kt = 0; kt < nk; kt++) {
        int buf = kt % 3;
        if (kt + 1 < nk) asm volatile("cp.async.wait_group 1;" ::: "memory");
        else             asm volatile("cp.async.wait_group 0;" ::: "memory");
        __syncthreads();
        if (kt + 2 < nk) ld(kt + 2, (kt + 2) % 3);

        const float* aw = awp + buf * APLANE;
        const float* bw = bwp + buf * BPLANE;
#pragma unroll
        for (int k8 = 0; k8 < 2; k8++) {
            uint32_t ua[2][4], ub[4][2];
#pragma unroll
            for (int mi = 0; mi < 2; mi++) {
                const float* ap = aw + mi * (16 * KP) + k8 * 8;
                CVT_TF32(ua[mi][0], ap[0]);
                CVT_TF32(ua[mi][1], ap[8 * KP]);
                CVT_TF32(ua[mi][2], ap[4]);
                CVT_TF32(ua[mi][3], ap[8 * KP + 4]);
            }
#pragma unroll
            for (int ni = 0; ni < 4; ni++) {
                const float* bp = bw + ni * (8 * KP) + k8 * 8;
                ub[ni][0] = __float_as_uint(bp[0]);
                ub[ni][1] = __float_as_uint(bp[4]);
            }
#pragma unroll
            for (int mi = 0; mi < 2; mi++)
#pragma unroll
                for (int ni = 0; ni < 4; ni++)
                    mma_tf32(acc[mi][ni], ua[mi], ub[ni]);
        }
    }

    int fc2 = (lane & 3) * 2;
    if (MODE == 1 || MODE == 2) {
#pragma unroll
        for (int mi = 0; mi < 2; mi++) {
            int r0 = rowBase + wm * 32 + mi * 16 + fr;
#pragma unroll
            for (int ni = 0; ni < 4; ni++) {
                int col = colBase + wn * 32 + ni * 8 + fc2;
                float b0 = bias[col], b1 = bias[col + 1];
                float v[4] = {acc[mi][ni][0] + b0, acc[mi][ni][1] + b1,
                              acc[mi][ni][2] + b0, acc[mi][ni][3] + b1};
                if (MODE == 2) {
#pragma unroll
                    for (int q = 0; q < 4; q++)
                        v[q] = 0.5f * v[q] * (1.f + erff(v[q] * 0.70710678118654752f));
                }
                if (col < N1) {
                    *(float2*)&C1[(size_t)r0 * s1 + col]       = make_float2(v[0], v[1]);
                    *(float2*)&C1[(size_t)(r0 + 8) * s1 + col] = make_float2(v[2], v[3]);
                } else {
                    int c2 = col - N1;
                    *(float2*)&C2[(size_t)r0 * s2 + c2]        = make_float2(v[0], v[1]);
                    *(float2*)&C2[(size_t)(r0 + 8) * s2 + c2]  = make_float2(v[2], v[3]);
                }
            }
        }
    } else {
        // fused LN epilogues: CTA owns full 64x128 rows (Ng=128, grid.x=1)
        float* st = sm;      // reuse smem as 64x128 tile (32KB)
        __syncthreads();     // all fragment reads done
#pragma unroll
        for (int mi = 0; mi < 2; mi++) {
            int rl = wm * 32 + mi * 16 + fr;
#pragma unroll
            for (int ni = 0; ni < 4; ni++) {
                int col = wn * 32 + ni * 8 + fc2;
                float b0 = bias[col], b1 = bias[col + 1];
                float v0 = acc[mi][ni][0] + b0, v1 = acc[mi][ni][1] + b1;
                float v2 = acc[mi][ni][2] + b0, v3 = acc[mi][ni][3] + b1;
                if (MODE == 6) {
                    v0 = 1.f / (1.f + __expf(-v0)); v1 = 1.f / (1.f + __expf(-v1));
                    v2 = 1.f / (1.f + __expf(-v2)); v3 = 1.f / (1.f + __expf(-v3));
                }
                *(float2*)&st[rl * 128 + col]       = make_float2(v0, v1);
                *(float2*)&st[(rl + 8) * 128 + col] = make_float2(v2, v3);
            }
        }
        __syncthreads();
#pragma unroll
        for (int r = 0; r < 8; r++) {
            int rl = wid * 8 + r;
            int grow = rowBase + rl;
            float4 cv = ((const float4*)(st + rl * 128))[lane];
            float4 v;
            if (MODE == 4 || MODE == 5) {
                float4 xv = *(const float4*)&xres[(size_t)grow * 128 + lane * 4];
                v = make_float4(cv.x + xv.x, cv.y + xv.y, cv.z + xv.z, cv.w + xv.w);
            } else { // MODE 6
                float4 xsp = *(const float4*)&C2[(size_t)grow * 256 + lane * 4];
                float4 xtp = *(const float4*)&C2[(size_t)grow * 256 + 128 + lane * 4];
                float4 xv  = *(const float4*)&xres[(size_t)grow * 128 + lane * 4];
                v = make_float4(cv.x * xsp.x + (1.f - cv.x) * xtp.x + xv.x,
                                cv.y * xsp.y + (1.f - cv.y) * xtp.y + xv.y,
                                cv.z * xsp.z + (1.f - cv.z) * xtp.z + xv.z,
                                cv.w * xsp.w + (1.f - cv.w) * xtp.w + xv.w);
            }
            float4 r4 = ln_compute(v, lng, lnb, lane);
            *(float4*)&C1[(size_t)grow * s1 + lane * 4] = r4;
        }
    }
}

// ---------------- fused GAT (online softmax, dst-centric) --------------------------
__global__ void k_gat(const float* __restrict__ att, const float* __restrict__ gat_b,
                      const float* __restrict__ lg, const float* __restrict__ lb) {
    int w = (blockIdx.x * blockDim.x + threadIdx.x) >> 5;   // row = (b*N+n)*T+t
    int lane = threadIdx.x & 31;
    if (w >= M_) return;
    int bn = w >> 3;
    int n = bn & (N_ - 1);
    int b = bn >> 10;
    int t = w & 7;

    const float4* xr4 = (const float4*)(g_xlr + (size_t)w * 1024 + 512);
    float4 xr[4], av[4];
#pragma unroll
    for (int h = 0; h < 4; h++) {
        xr[h] = xr4[h * 32 + lane];
        av[h] = ((const float4*)att)[h * 32 + lane];
    }
    float4 acc[4];
#pragma unroll
    for (int h = 0; h < 4; h++) acc[h] = make_float4(0.f, 0.f, 0.f, 0.f);
    float m[4] = {-INFINITY, -INFINITY, -INFINITY, -INFINITY};
    float s[4] = {0.f, 0.f, 0.f, 0.f};

    int deg = g_deg[n];
    if (deg > MAXDEG) deg = MAXDEG;
    const int* clist = g_csr + n * MAXDEG;

    for (int i = 0; i < deg; i++) {
        int src = clist[i];
        const float4* xl4 = (const float4*)(g_xlr + ((size_t)((b * N_ + src) * T_ + t)) * 1024);
        float4 xl[4];
        float lgt[4];
#pragma unroll
        for (int h = 0; h < 4; h++) {
            float4 a = xl4[h * 32 + lane];
            xl[h] = a;
            float v0 = a.x + xr[h].x; v0 = v0 > 0.f ? v0 : 0.2f * v0;
            float v1 = a.y + xr[h].y; v1 = v1 > 0.f ? v1 : 0.2f * v1;
            float v2 = a.z + xr[h].z; v2 = v2 > 0.f ? v2 : 0.2f * v2;
            float v3 = a.w + xr[h].w; v3 = v3 > 0.f ? v3 : 0.2f * v3;
            lgt[h] = warp_sum(av[h].x * v0 + av[h].y * v1 + av[h].z * v2 + av[h].w * v3);
        }
#pragma unroll
        for (int h = 0; h < 4; h++) {
            float nm = fmaxf(m[h], lgt[h]);
            float e0 = __expf(m[h] - nm);
            float e1 = __expf(lgt[h] - nm);
            s[h] = s[h] * e0 + e1;
            acc[h].x = acc[h].x * e0 + e1 * xl[h].x;
            acc[h].y = acc[h].y * e0 + e1 * xl[h].y;
            acc[h].z = acc[h].z * e0 + e1 * xl[h].z;
            acc[h].w = acc[h].w * e0 + e1 * xl[h].w;
            m[h] = nm;
        }
    }

    float4 o = make_float4(0.f, 0.f, 0.f, 0.f);
#pragma unroll
    for (int h = 0; h < 4; h++) {
        float r = 0.25f / s[h];
        o.x += acc[h].x * r; o.y += acc[h].y * r;
        o.z += acc[h].z * r; o.w += acc[h].w * r;
    }
    float4 gb = *(const float4*)&gat_b[lane * 4];
    o.x += gb.x; o.y += gb.y; o.z += gb.z; o.w += gb.w;

    float4 r4 = ln_compute(o, lg, lb, lane);
    *(float4*)&g_cat[(size_t)w * 256 + lane * 4] = r4;
}

// ---------------- temporal attention ------------------------------------------------
__global__ void k_attn() {
    int w = blockIdx.x * 4 + (threadIdx.x >> 5);
    int lane = threadIdx.x & 31;
    if (w >= (B_ * N_) * H_) return;
    int bn = w >> 2;
    int h = w & 3;
    float q[8], k[8], v[8];
#pragma unroll
    for (int t = 0; t < 8; t++) {
        size_t base = ((size_t)bn * 8 + t) * 384 + h * 32 + lane;
        q[t] = g_qkv[base];
        k[t] = g_qkv[base + 128];
        v[t] = g_qkv[base + 256];
    }
    const float scale = 0.17677669529663687f;
#pragma unroll
    for (int t = 0; t < 8; t++) {
        float sc[8];
#pragma unroll
        for (int s = 0; s < 8; s++) sc[s] = warp_sum(q[t] * k[s]) * scale;
        float mx = sc[0];
#pragma unroll
        for (int s = 1; s < 8; s++) mx = fmaxf(mx, sc[s]);
        float den = 0.f;
#pragma unroll
        for (int s = 0; s < 8; s++) { sc[s] = __expf(sc[s] - mx); den += sc[s]; }
        float inv = 1.f / den;
        float o = 0.f;
#pragma unroll
        for (int s = 0; s < 8; s++) o += sc[s] * v[s];
        g_attno[((size_t)bn * 8 + t) * D_ + h * 32 + lane] = o * inv;
    }
}

// ---------------- launch ---------------------------------------------------------------
extern "C" void kernel_launch(void* const* d_in, const int* in_sizes, int n_in,
                              void* d_out, int out_size) {
    const float* x      = (const float*)d_in[0];
    const int*   edges  = (const int*)  d_in[1];
    const float* gat_att= (const float*)d_in[4];
    const float* gat_b  = (const float*)d_in[5];
    const float* in_b   = (const float*)d_in[7];
    const float* out_b  = (const float*)d_in[9];
    const float* ffn_b1 = (const float*)d_in[11];
    const float* ffn_b2 = (const float*)d_in[13];
    const float* fus_b  = (const float*)d_in[15];
    const float* lns_g  = (const float*)d_in[16];
    const float* lns_b  = (const float*)d_in[17];
    const float* lnt1_g = (const float*)d_in[18];
    const float* lnt1_b = (const float*)d_in[19];
    const float* lnt2_g = (const float*)d_in[20];
    const float* lnt2_b = (const float*)d_in[21];
    const float* lnf_g  = (const float*)d_in[22];
    const float* lnf_b  = (const float*)d_in[23];
    float* out = (float*)d_out;

    float *p_xlr, *p_qkv, *p_attno, *p_x1, *p_hid, *p_cat;
    float *p_bxq, *p_Bxq, *p_Bout, *p_Bffn1, *p_Bffn2, *p_Bfus;
    cudaGetSymbolAddress((void**)&p_xlr,   g_xlr);
    cudaGetSymbolAddress((void**)&p_qkv,   g_qkv);
    cudaGetSymbolAddress((void**)&p_attno, g_attno);
    cudaGetSymbolAddress((void**)&p_x1,    g_x1);
    cudaGetSymbolAddress((void**)&p_hid,   g_hid);
    cudaGetSymbolAddress((void**)&p_cat,   g_cat);
    cudaGetSymbolAddress((void**)&p_bxq,   g_bias_xq);
    cudaGetSymbolAddress((void**)&p_Bxq,   g_Bxq);
    cudaGetSymbolAddress((void**)&p_Bout,  g_Bout);
    cudaGetSymbolAddress((void**)&p_Bffn1, g_Bffn1);
    cudaGetSymbolAddress((void**)&p_Bffn2, g_Bffn2);
    cudaGetSymbolAddress((void**)&p_Bfus,  g_Bfus);

    cudaFuncSetAttribute(hgemm<1>, cudaFuncAttributeMaxDynamicSharedMemorySize, SMEMSZ);
    cudaFuncSetAttribute(hgemm<2>, cudaFuncAttributeMaxDynamicSharedMemorySize, SMEMSZ);
    cudaFuncSetAttribute(hgemm<4>, cudaFuncAttributeMaxDynamicSharedMemorySize, SMEMSZ);
    cudaFuncSetAttribute(hgemm<5>, cudaFuncAttributeMaxDynamicSharedMemorySize, SMEMSZ);
    cudaFuncSetAttribute(hgemm<6>, cudaFuncAttributeMaxDynamicSharedMemorySize, SMEMSZ);

    static cudaStream_t s1 = nullptr;
    static cudaEvent_t evFork = nullptr, evJoin = nullptr;
    if (s1 == nullptr) {
        cudaStreamCreateWithFlags(&s1, cudaStreamNonBlocking);
        cudaEventCreateWithFlags(&evFork, cudaEventDisableTiming);
        cudaEventCreateWithFlags(&evJoin, cudaEventDisableTiming);
    }

    // prep: CSR on s1; bias+packw on main
    k_csr0<<<4, 256, 0, s1>>>();
    k_scatter<<<E_ / 256, 256, 0, s1>>>(edges);
    k_bias<<<6, 256>>>(in_b);
    k_packw<<<dim3(256, 7), 256>>>((const float*)d_in[2], (const float*)d_in[3],
                                   (const float*)d_in[6], (const float*)d_in[8],
                                   (const float*)d_in[10], (const float*)d_in[12],
                                   (const float*)d_in[14]);

    // merged spatial+qkv: [xlr | qkv] = x @ [Wl|Wr|Wqkv]
    hgemm<1><<<dim3(11, 256), 256, SMEMSZ>>>(x, p_Bxq, p_bxq,
                                             p_xlr, 1024, 1024, p_qkv, 384, 128,
                                             nullptr, nullptr, nullptr);

    // fork: GAT branch on s1
    cudaEventRecord(evFork, 0);
    cudaStreamWaitEvent(s1, evFork, 0);
    k_gat<<<M_ / 8, 256, 0, s1>>>(gat_att, gat_b, lns_g, lns_b);
    cudaEventRecord(evJoin, s1);

    // temporal branch (default stream)
    k_attn<<<(B_ * N_ * H_) / 4, 128>>>();
    // out-proj + residual + LN1 -> x1
    hgemm<4><<<dim3(1, 256), 256, SMEMSZ>>>(p_attno, p_Bout, out_b,
                                            p_x1, 128, 128, nullptr, 0, 128,
                                            x, lnt1_g, lnt1_b);
    // ffn1 + GELU -> hid
    hgemm<2><<<dim3(4, 256), 256, SMEMSZ>>>(p_x1, p_Bffn1, ffn_b1,
                                            p_hid, 512, 512, nullptr, 0, 128,
                                            nullptr, nullptr, nullptr);
    // ffn2 + residual + LN2 -> cat[:,128:]
    hgemm<5><<<dim3(1, 256), 256, SMEMSZ>>>(p_hid, p_Bffn2, ffn_b2,
                                            p_cat + 128, 128, 256, nullptr, 0, 512,
                                            p_x1, lnt2_g, lnt2_b);

    // join: fusion needs g_cat[:, :128] from the GAT branch
    cudaStreamWaitEvent(0, evJoin, 0);
    // fusion + gate + final LN -> out
    hgemm<6><<<dim3(1, 256), 256, SMEMSZ>>>(p_cat, p_Bfus, fus_b,
                                            out, 128, 128, p_cat, 256, 256,
                                            x, lnf_g, lnf_b);
}

// round 13
// speedup vs baseline: 1.1974x; 1.0099x over previous
#include <cuda_runtime.h>
#include <cuda_bf16.h>
#include <math.h>
#include <stdint.h>

#define B_  2
#define N_  1024
#define T_  8
#define D_  128
#define H_  4
#define E_  8192
#define M_  16384
#define MAXDEG 128

// ---------------- scratch (device globals) ----------------------------------
__device__ __align__(256) float g_xlr[(size_t)M_ * 1024];   // [xl(512)|xr(512)]
__device__ __align__(256) float g_qkv[(size_t)M_ * 384];
__device__ __align__(256) float g_attno[(size_t)M_ * 128];
__device__ __align__(256) float g_x1[(size_t)M_ * 128];
__device__ __align__(256) float g_hid[(size_t)M_ * 512];
__device__ __align__(256) float g_cat[(size_t)M_ * 256];    // [x_sp | x_tp]
// packed tf32 weights, [n][k] layout (pre-rounded via cvt.rna)
__device__ __align__(256) float g_Bxq[1408 * 128];          // [Wl|Wr|Wqkv]
__device__ __align__(256) float g_bias_xq[1408];            // [0(1024) | in_b(384)]
__device__ __align__(256) float g_Bout[128 * 128];
__device__ __align__(256) float g_Bffn1[512 * 128];
__device__ __align__(256) float g_Bffn2[128 * 512];
__device__ __align__(256) float g_Bfus[128 * 256];
// CSR
__device__ int g_deg[N_];
__device__ int g_csr[N_ * MAXDEG];

// ---------------- helpers ------------------------------------------------------
__device__ __forceinline__ float warp_sum(float v) {
#pragma unroll
    for (int o = 16; o; o >>= 1) v += __shfl_xor_sync(0xFFFFFFFFu, v, o);
    return v;
}
__device__ __forceinline__ uint32_t smem_u32(const void* p) {
    uint32_t a;
    asm("{ .reg .u64 t; cvta.to.shared.u64 t, %1; cvt.u32.u64 %0, t; }"
        : "=r"(a) : "l"(p));
    return a;
}
#define CP16(dst, src) \
    asm volatile("cp.async.cg.shared.global [%0], [%1], 16;" :: "r"(dst), "l"(src))
#define CVT_TF32(u, f) asm("cvt.rna.tf32.f32 %0, %1;" : "=r"(u) : "f"(f))

__device__ __forceinline__ void mma_tf32(float c[4], const uint32_t a[4],
                                         const uint32_t b[2]) {
    asm volatile(
        "mma.sync.aligned.m16n8k8.row.col.f32.tf32.tf32.f32 "
        "{%0,%1,%2,%3}, {%4,%5,%6,%7}, {%8,%9}, {%0,%1,%2,%3};"
        : "+f"(c[0]), "+f"(c[1]), "+f"(c[2]), "+f"(c[3])
        : "r"(a[0]), "r"(a[1]), "r"(a[2]), "r"(a[3]), "r"(b[0]), "r"(b[1]));
}

__device__ __forceinline__ float4 ln_compute(float4 v, const float* g, const float* b,
                                             int lane) {
    float mean = warp_sum(v.x + v.y + v.z + v.w) * (1.f / 128.f);
    float4 c = make_float4(v.x - mean, v.y - mean, v.z - mean, v.w - mean);
    float var = warp_sum(c.x * c.x + c.y * c.y + c.z * c.z + c.w * c.w) * (1.f / 128.f);
    float rs = rsqrtf(var + 1e-5f);
    float4 gv = *(const float4*)&g[lane * 4];
    float4 bv = *(const float4*)&b[lane * 4];
    return make_float4(c.x * rs * gv.x + bv.x, c.y * rs * gv.y + bv.y,
                       c.z * rs * gv.z + bv.z, c.w * rs * gv.w + bv.w);
}

// ---------------- init + CSR + bias_xq -------------------------------------------
__global__ void k_bias(const float* __restrict__ in_b) {
    int i = blockIdx.x * blockDim.x + threadIdx.x;
    if (i < 1408) g_bias_xq[i] = (i < 1024) ? 0.f : in_b[i - 1024];
}
__global__ void k_csr0() {
    int i = blockIdx.x * blockDim.x + threadIdx.x;
    if (i < N_) { g_deg[i] = 1; g_csr[i * MAXDEG] = i; }   // self loop
}
__global__ void k_scatter(const int* __restrict__ edges) {
    int e = blockIdx.x * blockDim.x + threadIdx.x;
    if (e >= E_) return;
    int s = edges[e], d = edges[E_ + e];
    int pos = atomicAdd(&g_deg[d], 1);
    if (pos < MAXDEG) g_csr[d * MAXDEG + pos] = s;
}

// ---------------- weight packing -----------------------------------------------
__global__ void k_packw(const float* wl, const float* wr, const float* inw,
                        const float* outw, const float* f1w, const float* f2w,
                        const float* fw) {
    int job = blockIdx.y;
    int idx = blockIdx.x * 256 + threadIdx.x;
    const float* W; float* Bo; int K, Nw, coff = 0;
    switch (job) {
        case 0: W = wl;   Bo = g_Bxq;   K = 128; Nw = 512; break;
        case 1: W = wr;   Bo = g_Bxq;   K = 128; Nw = 512; coff = 512; break;
        case 2: W = inw;  Bo = g_Bxq;   K = 128; Nw = 384; coff = 1024; break;
        case 3: W = outw; Bo = g_Bout;  K = 128; Nw = 128; break;
        case 4: W = f1w;  Bo = g_Bffn1; K = 128; Nw = 512; break;
        case 5: W = f2w;  Bo = g_Bffn2; K = 512; Nw = 128; break;
        default:W = fw;   Bo = g_Bfus;  K = 256; Nw = 128; break;
    }
    if (idx >= K * Nw) return;
    int k = idx / Nw, n = idx % Nw;
    uint32_t u;
    CVT_TF32(u, W[idx]);
    Bo[(size_t)(coff + n) * K + k] = __uint_as_float(u);
}

// ---------------- tf32 mma.sync GEMM, templated epilogue --------------------------
// MODE 1: +bias -> C1 (stride s1)          [plain]
// MODE 2: +bias+GELU -> C1 (stride s1)
// MODE 4: +bias, LN(xres + C) -> C1        [out-proj + lnt1]
// MODE 5: +bias, LN(xres + C) -> C1        [ffn2 + lnt2 -> cat+128]
// MODE 6: +bias, sigmoid gate; xsp=C2[r*256], xtp=C2[r*256+128];
//         LN(g*xsp+(1-g)*xtp+xres) -> C1   [fusion + final]
#define KP 20
#define APLANE (64 * KP)
#define BPLANE (128 * KP)
#define SMEMSZ ((APLANE + BPLANE) * 3 * 4)

template<int MODE>
__global__ void __launch_bounds__(256, 3) hgemm(
        const float* __restrict__ A, const float* __restrict__ Bp,
        const float* __restrict__ bias,
        float* __restrict__ C1, int s1,
        float* __restrict__ C2,
        int K,
        const float* __restrict__ xres,
        const float* __restrict__ lng, const float* __restrict__ lnb) {
    extern __shared__ float sm[];
    float* sA = sm;                    // [3][64][KP]
    float* sB = sm + 3 * APLANE;       // [3][128][KP]
    int tid = threadIdx.x, wid = tid >> 5, lane = tid & 31;
    int wm = wid >> 2, wn = wid & 3;
    int rowBase = blockIdx.y * 64, colBase = blockIdx.x * 128;
    int nk = K >> 4;

    float acc[2][4][4];
#pragma unroll
    for (int i = 0; i < 2; i++)
#pragma unroll
        for (int j = 0; j < 4; j++)
#pragma unroll
            for (int q = 0; q < 4; q++) acc[i][j][q] = 0.f;

    int ar = tid >> 2, aq = tid & 3;
    int br = tid >> 1, bq = (tid & 1) * 2;
    const char* Asrc = (const char*)(A + (size_t)(rowBase + ar) * K + aq * 4);
    const char* Bsrc = (const char*)(Bp + (size_t)(colBase + br) * K + bq * 4);
    uint32_t dA = smem_u32(sA) + (uint32_t)(ar * KP + aq * 4) * 4;
    uint32_t dB = smem_u32(sB) + (uint32_t)(br * KP + bq * 4) * 4;

    auto ld = [&](int kt, int buf) {
        CP16(dA + buf * (APLANE * 4), Asrc + (size_t)kt * 64);
        CP16(dB + buf * (BPLANE * 4), Bsrc + (size_t)kt * 64);
        CP16(dB + buf * (BPLANE * 4) + 16, Bsrc + (size_t)kt * 64 + 16);
        asm volatile("cp.async.commit_group;" ::: "memory");
    };

    ld(0, 0);
    if (nk > 1) ld(1, 1);

    int fr = lane >> 2, fq = lane & 3;
    const float* awp = sA + (wm * 32 + fr) * KP + fq;
    const float* bwp = sB + (wn * 32 + fr) * KP + fq;

    for (int kt = 0; kt < nk; kt++) {
        int buf = kt % 3;
        if (kt + 1 < nk) asm volatile("cp.async.wait_group 1;" ::: "memory");
        else             asm volatile("cp.async.wait_group 0;" ::: "memory");
        __syncthreads();
        if (kt + 2 < nk) ld(kt + 2, (kt + 2) % 3);

        const float* aw = awp + buf * APLANE;
        const float* bw = bwp + buf * BPLANE;
#pragma unroll
        for (int k8 = 0; k8 < 2; k8++) {
            uint32_t ua[2][4], ub[4][2];
#pragma unroll
            for (int mi = 0; mi < 2; mi++) {
                const float* ap = aw + mi * (16 * KP) + k8 * 8;
                CVT_TF32(ua[mi][0], ap[0]);
                CVT_TF32(ua[mi][1], ap[8 * KP]);
                CVT_TF32(ua[mi][2], ap[4]);
                CVT_TF32(ua[mi][3], ap[8 * KP + 4]);
            }
#pragma unroll
            for (int ni = 0; ni < 4; ni++) {
                const float* bp = bw + ni * (8 * KP) + k8 * 8;
                ub[ni][0] = __float_as_uint(bp[0]);
                ub[ni][1] = __float_as_uint(bp[4]);
            }
#pragma unroll
            for (int mi = 0; mi < 2; mi++)
#pragma unroll
                for (int ni = 0; ni < 4; ni++)
                    mma_tf32(acc[mi][ni], ua[mi], ub[ni]);
        }
    }

    int fc2 = (lane & 3) * 2;
    if (MODE == 1 || MODE == 2) {
#pragma unroll
        for (int mi = 0; mi < 2; mi++) {
            int r0 = rowBase + wm * 32 + mi * 16 + fr;
#pragma unroll
            for (int ni = 0; ni < 4; ni++) {
                int col = colBase + wn * 32 + ni * 8 + fc2;
                float b0 = bias[col], b1 = bias[col + 1];
                float v[4] = {acc[mi][ni][0] + b0, acc[mi][ni][1] + b1,
                              acc[mi][ni][2] + b0, acc[mi][ni][3] + b1};
                if (MODE == 2) {
#pragma unroll
                    for (int q = 0; q < 4; q++)
                        v[q] = 0.5f * v[q] * (1.f + erff(v[q] * 0.70710678118654752f));
                }
                *(float2*)&C1[(size_t)r0 * s1 + col]       = make_float2(v[0], v[1]);
                *(float2*)&C1[(size_t)(r0 + 8) * s1 + col] = make_float2(v[2], v[3]);
            }
        }
    } else {
        // fused LN epilogues: CTA owns full 64x128 rows (Ng=128, grid.x=1)
        float* st = sm;      // reuse smem as 64x128 tile (32KB)
        __syncthreads();     // all fragment reads done
#pragma unroll
        for (int mi = 0; mi < 2; mi++) {
            int rl = wm * 32 + mi * 16 + fr;
#pragma unroll
            for (int ni = 0; ni < 4; ni++) {
                int col = wn * 32 + ni * 8 + fc2;
                float b0 = bias[col], b1 = bias[col + 1];
                float v0 = acc[mi][ni][0] + b0, v1 = acc[mi][ni][1] + b1;
                float v2 = acc[mi][ni][2] + b0, v3 = acc[mi][ni][3] + b1;
                if (MODE == 6) {
                    v0 = 1.f / (1.f + __expf(-v0)); v1 = 1.f / (1.f + __expf(-v1));
                    v2 = 1.f / (1.f + __expf(-v2)); v3 = 1.f / (1.f + __expf(-v3));
                }
                *(float2*)&st[rl * 128 + col]       = make_float2(v0, v1);
                *(float2*)&st[(rl + 8) * 128 + col] = make_float2(v2, v3);
            }
        }
        __syncthreads();
#pragma unroll
        for (int r = 0; r < 8; r++) {
            int rl = wid * 8 + r;
            int grow = rowBase + rl;
            float4 cv = ((const float4*)(st + rl * 128))[lane];
            float4 v;
            if (MODE == 4 || MODE == 5) {
                float4 xv = *(const float4*)&xres[(size_t)grow * 128 + lane * 4];
                v = make_float4(cv.x + xv.x, cv.y + xv.y, cv.z + xv.z, cv.w + xv.w);
            } else { // MODE 6
                float4 xsp = *(const float4*)&C2[(size_t)grow * 256 + lane * 4];
                float4 xtp = *(const float4*)&C2[(size_t)grow * 256 + 128 + lane * 4];
                float4 xv  = *(const float4*)&xres[(size_t)grow * 128 + lane * 4];
                v = make_float4(cv.x * xsp.x + (1.f - cv.x) * xtp.x + xv.x,
                                cv.y * xsp.y + (1.f - cv.y) * xtp.y + xv.y,
                                cv.z * xsp.z + (1.f - cv.z) * xtp.z + xv.z,
                                cv.w * xsp.w + (1.f - cv.w) * xtp.w + xv.w);
            }
            float4 r4 = ln_compute(v, lng, lnb, lane);
            *(float4*)&C1[(size_t)grow * s1 + lane * 4] = r4;
        }
    }
}

// ---------------- fused GAT (online softmax, dst-centric) --------------------------
__global__ void k_gat(const float* __restrict__ att, const float* __restrict__ gat_b,
                      const float* __restrict__ lg, const float* __restrict__ lb) {
    int w = (blockIdx.x * blockDim.x + threadIdx.x) >> 5;   // row = (b*N+n)*T+t
    int lane = threadIdx.x & 31;
    if (w >= M_) return;
    int bn = w >> 3;
    int n = bn & (N_ - 1);
    int b = bn >> 10;
    int t = w & 7;

    const float4* xr4 = (const float4*)(g_xlr + (size_t)w * 1024 + 512);
    float4 xr[4], av[4];
#pragma unroll
    for (int h = 0; h < 4; h++) {
        xr[h] = xr4[h * 32 + lane];
        av[h] = ((const float4*)att)[h * 32 + lane];
    }
    float4 acc[4];
#pragma unroll
    for (int h = 0; h < 4; h++) acc[h] = make_float4(0.f, 0.f, 0.f, 0.f);
    float m[4] = {-INFINITY, -INFINITY, -INFINITY, -INFINITY};
    float s[4] = {0.f, 0.f, 0.f, 0.f};

    int deg = g_deg[n];
    if (deg > MAXDEG) deg = MAXDEG;
    const int* clist = g_csr + n * MAXDEG;

    for (int i = 0; i < deg; i++) {
        int src = clist[i];
        const float4* xl4 = (const float4*)(g_xlr + ((size_t)((b * N_ + src) * T_ + t)) * 1024);
        float4 xl[4];
        float lgt[4];
#pragma unroll
        for (int h = 0; h < 4; h++) {
            float4 a = xl4[h * 32 + lane];
            xl[h] = a;
            float v0 = a.x + xr[h].x; v0 = v0 > 0.f ? v0 : 0.2f * v0;
            float v1 = a.y + xr[h].y; v1 = v1 > 0.f ? v1 : 0.2f * v1;
            float v2 = a.z + xr[h].z; v2 = v2 > 0.f ? v2 : 0.2f * v2;
            float v3 = a.w + xr[h].w; v3 = v3 > 0.f ? v3 : 0.2f * v3;
            lgt[h] = warp_sum(av[h].x * v0 + av[h].y * v1 + av[h].z * v2 + av[h].w * v3);
        }
#pragma unroll
        for (int h = 0; h < 4; h++) {
            float nm = fmaxf(m[h], lgt[h]);
            float e0 = __expf(m[h] - nm);
            float e1 = __expf(lgt[h] - nm);
            s[h] = s[h] * e0 + e1;
            acc[h].x = acc[h].x * e0 + e1 * xl[h].x;
            acc[h].y = acc[h].y * e0 + e1 * xl[h].y;
            acc[h].z = acc[h].z * e0 + e1 * xl[h].z;
            acc[h].w = acc[h].w * e0 + e1 * xl[h].w;
            m[h] = nm;
        }
    }

    float4 o = make_float4(0.f, 0.f, 0.f, 0.f);
#pragma unroll
    for (int h = 0; h < 4; h++) {
        float r = 0.25f / s[h];
        o.x += acc[h].x * r; o.y += acc[h].y * r;
        o.z += acc[h].z * r; o.w += acc[h].w * r;
    }
    float4 gb = *(const float4*)&gat_b[lane * 4];
    o.x += gb.x; o.y += gb.y; o.z += gb.z; o.w += gb.w;

    float4 r4 = ln_compute(o, lg, lb, lane);
    *(float4*)&g_cat[(size_t)w * 256 + lane * 4] = r4;
}

// ---------------- temporal attention ------------------------------------------------
__global__ void k_attn() {
    int w = blockIdx.x * 4 + (threadIdx.x >> 5);
    int lane = threadIdx.x & 31;
    if (w >= (B_ * N_) * H_) return;
    int bn = w >> 2;
    int h = w & 3;
    float q[8], k[8], v[8];
#pragma unroll
    for (int t = 0; t < 8; t++) {
        size_t base = ((size_t)bn * 8 + t) * 384 + h * 32 + lane;
        q[t] = g_qkv[base];
        k[t] = g_qkv[base + 128];
        v[t] = g_qkv[base + 256];
    }
    const float scale = 0.17677669529663687f;
#pragma unroll
    for (int t = 0; t < 8; t++) {
        float sc[8];
#pragma unroll
        for (int s = 0; s < 8; s++) sc[s] = warp_sum(q[t] * k[s]) * scale;
        float mx = sc[0];
#pragma unroll
        for (int s = 1; s < 8; s++) mx = fmaxf(mx, sc[s]);
        float den = 0.f;
#pragma unroll
        for (int s = 0; s < 8; s++) { sc[s] = __expf(sc[s] - mx); den += sc[s]; }
        float inv = 1.f / den;
        float o = 0.f;
#pragma unroll
        for (int s = 0; s < 8; s++) o += sc[s] * v[s];
        g_attno[((size_t)bn * 8 + t) * D_ + h * 32 + lane] = o * inv;
    }
}

// ---------------- launch ---------------------------------------------------------------
extern "C" void kernel_launch(void* const* d_in, const int* in_sizes, int n_in,
                              void* d_out, int out_size) {
    const float* x      = (const float*)d_in[0];
    const int*   edges  = (const int*)  d_in[1];
    const float* gat_att= (const float*)d_in[4];
    const float* gat_b  = (const float*)d_in[5];
    const float* in_b   = (const float*)d_in[7];
    const float* out_b  = (const float*)d_in[9];
    const float* ffn_b1 = (const float*)d_in[11];
    const float* ffn_b2 = (const float*)d_in[13];
    const float* fus_b  = (const float*)d_in[15];
    const float* lns_g  = (const float*)d_in[16];
    const float* lns_b  = (const float*)d_in[17];
    const float* lnt1_g = (const float*)d_in[18];
    const float* lnt1_b = (const float*)d_in[19];
    const float* lnt2_g = (const float*)d_in[20];
    const float* lnt2_b = (const float*)d_in[21];
    const float* lnf_g  = (const float*)d_in[22];
    const float* lnf_b  = (const float*)d_in[23];
    float* out = (float*)d_out;

    float *p_xlr, *p_qkv, *p_attno, *p_x1, *p_hid, *p_cat;
    float *p_bxq, *p_Bxq, *p_Bout, *p_Bffn1, *p_Bffn2, *p_Bfus;
    cudaGetSymbolAddress((void**)&p_xlr,   g_xlr);
    cudaGetSymbolAddress((void**)&p_qkv,   g_qkv);
    cudaGetSymbolAddress((void**)&p_attno, g_attno);
    cudaGetSymbolAddress((void**)&p_x1,    g_x1);
    cudaGetSymbolAddress((void**)&p_hid,   g_hid);
    cudaGetSymbolAddress((void**)&p_cat,   g_cat);
    cudaGetSymbolAddress((void**)&p_bxq,   g_bias_xq);
    cudaGetSymbolAddress((void**)&p_Bxq,   g_Bxq);
    cudaGetSymbolAddress((void**)&p_Bout,  g_Bout);
    cudaGetSymbolAddress((void**)&p_Bffn1, g_Bffn1);
    cudaGetSymbolAddress((void**)&p_Bffn2, g_Bffn2);
    cudaGetSymbolAddress((void**)&p_Bfus,  g_Bfus);

    cudaFuncSetAttribute(hgemm<1>, cudaFuncAttributeMaxDynamicSharedMemorySize, SMEMSZ);
    cudaFuncSetAttribute(hgemm<2>, cudaFuncAttributeMaxDynamicSharedMemorySize, SMEMSZ);
    cudaFuncSetAttribute(hgemm<4>, cudaFuncAttributeMaxDynamicSharedMemorySize, SMEMSZ);
    cudaFuncSetAttribute(hgemm<5>, cudaFuncAttributeMaxDynamicSharedMemorySize, SMEMSZ);
    cudaFuncSetAttribute(hgemm<6>, cudaFuncAttributeMaxDynamicSharedMemorySize, SMEMSZ);

    static cudaStream_t s1 = nullptr;
    static cudaEvent_t evFork = nullptr, evJoin = nullptr;
    if (s1 == nullptr) {
        cudaStreamCreateWithFlags(&s1, cudaStreamNonBlocking);
        cudaEventCreateWithFlags(&evFork, cudaEventDisableTiming);
        cudaEventCreateWithFlags(&evJoin, cudaEventDisableTiming);
    }

    // prep: CSR on s1; bias+packw on main
    k_csr0<<<4, 256, 0, s1>>>();
    k_scatter<<<E_ / 256, 256, 0, s1>>>(edges);
    k_bias<<<6, 256>>>(in_b);
    k_packw<<<dim3(256, 7), 256>>>((const float*)d_in[2], (const float*)d_in[3],
                                   (const float*)d_in[6], (const float*)d_in[8],
                                   (const float*)d_in[10], (const float*)d_in[12],
                                   (const float*)d_in[14]);

    // fork after packw: spatial branch (xlr GEMM + GAT) on s1, concurrent with
    // the whole temporal branch on the main stream.
    cudaEventRecord(evFork, 0);
    cudaStreamWaitEvent(s1, evFork, 0);

    // s1: xlr = x @ [Wl|Wr]  (N=1024), then fused GAT -> g_cat[:, :128]
    hgemm<1><<<dim3(8, 256), 256, SMEMSZ, s1>>>(x, p_Bxq, p_bxq,
                                                p_xlr, 1024, nullptr, 128,
                                                nullptr, nullptr, nullptr);
    k_gat<<<M_ / 8, 256, 0, s1>>>(gat_att, gat_b, lns_g, lns_b);
    cudaEventRecord(evJoin, s1);

    // main: qkv = x @ Wqkv (N=384) -> temporal chain
    hgemm<1><<<dim3(3, 256), 256, SMEMSZ>>>(x, p_Bxq + 1024 * 128, p_bxq + 1024,
                                            p_qkv, 384, nullptr, 128,
                                            nullptr, nullptr, nullptr);
    k_attn<<<(B_ * N_ * H_) / 4, 128>>>();
    hgemm<4><<<dim3(1, 256), 256, SMEMSZ>>>(p_attno, p_Bout, out_b,
                                            p_x1, 128, nullptr, 128,
                                            x, lnt1_g, lnt1_b);
    hgemm<2><<<dim3(4, 256), 256, SMEMSZ>>>(p_x1, p_Bffn1, ffn_b1,
                                            p_hid, 512, nullptr, 128,
                                            nullptr, nullptr, nullptr);
    hgemm<5><<<dim3(1, 256), 256, SMEMSZ>>>(p_hid, p_Bffn2, ffn_b2,
                                            p_cat + 128, 256, nullptr, 512,
                                            p_x1, lnt2_g, lnt2_b);

    // join: fusion needs g_cat[:, :128] from the GAT branch
    cudaStreamWaitEvent(0, evJoin, 0);
    hgemm<6><<<dim3(1, 256), 256, SMEMSZ>>>(p_cat, p_Bfus, fus_b,
                                            out, 128, p_cat, 256,
                                            x, lnf_g, lnf_b);
}